// round 11
// baseline (speedup 1.0000x reference)
#include <cuda_runtime.h>
#include <cuda_fp16.h>

static constexpr int N = 100000;
static constexpr int E = 1600000;
static constexpr int SCAN_B = 512;
static constexpr int NB_SCAN = (N + SCAN_B - 1) / SCAN_B;   // 196

// ---- zeroed-per-launch region (single memset): g_cw[N] | g_state[NB] | ticket ----
__device__ unsigned long long g_zero[N + NB_SCAN + 1];
#define g_cw     (g_zero)                  // packed: count<<40 | wdeg*2^24
#define g_state  (g_zero + N)              // lookback: flag<<62 | inclusive/aggregate
#define g_ticket (g_zero + N + NB_SCAN)

__device__ float   g_dinv[N];
__device__ int     g_cnt[N];
__device__ int     g_rs[N];
__device__ int     g_rank[E];              // per-edge rank within its dst bucket
__device__ int2    g_edge[E];              // {src, w*dinv[src] as bits}
__device__ __half2 g_y1h[N * 32];          // x @ W1, raw, fp16 (128 B/row)
__device__ float   g_h [N * 64];           // relu'd hidden, fp32
__device__ __half2 g_y2h[N * 16];          // h @ W2, raw, fp16 (64 B/row)

// ---- count + weighted degree; atomic return value gives the edge's bucket rank ----
__global__ void k_prep(const int* __restrict__ ei, const float* __restrict__ ew) {
    int t = blockIdx.x * blockDim.x + threadIdx.x;
    int e = t * 4;
    if (e >= E) return;
    int4   d4 = *((const int4*)(ei + E + e));
    float4 w4 = *((const float4*)(ew + e));
    int4 r;
    #pragma unroll
    for (int k = 0; k < 4; k++) {
        int d = (&d4.x)[k];
        float w = (&w4.x)[k];
        if ((unsigned)d >= (unsigned)N) d = 0;
        unsigned long long v = (1ULL << 40) |
            (unsigned long long)(unsigned int)__float2uint_rn(w * 16777216.0f);
        unsigned long long old = atomicAdd(&g_cw[d], v);
        (&r.x)[k] = (int)(old >> 40);      // rank of this edge within dst d
    }
    *((int4*)(g_rank + e)) = r;
}

// ---- single-kernel scan: decode + decoupled-lookback prefix + rs/dinv ----
__global__ void __launch_bounds__(SCAN_B) k_scan() {
    __shared__ int wsum[16];
    __shared__ int sh_bid;
    __shared__ unsigned sh_excl;
    __shared__ int sh_total;
    int t = threadIdx.x, lane = t & 31, wid = t >> 5;

    if (t == 0) sh_bid = (int)atomicAdd(g_ticket, 1ULL);   // ordered tile id
    __syncthreads();
    int bid = sh_bid;
    int g = bid * SCAN_B + t;

    int v = 0;
    if (g < N) {
        unsigned long long p = g_cw[g];
        v = (int)(p >> 40);
        float wdeg = (float)(p & ((1ULL << 40) - 1)) * (1.0f / 16777216.0f);
        g_cnt[g] = v;
        g_dinv[g] = rsqrtf(1.0f + wdeg);
    }
    int s = v;
    #pragma unroll
    for (int o = 1; o < 32; o <<= 1) {
        int n = __shfl_up_sync(0xffffffffu, s, o);
        if (lane >= o) s += n;
    }
    if (lane == 31) wsum[wid] = s;
    __syncthreads();
    if (wid == 0) {
        int ws = (lane < 16) ? wsum[lane] : 0;
        #pragma unroll
        for (int o = 1; o < 16; o <<= 1) {
            int n = __shfl_up_sync(0xffffffffu, ws, o);
            if (lane >= o) ws += n;
        }
        if (lane < 16) wsum[lane] = ws;
    }
    __syncthreads();
    s += wid ? wsum[wid - 1] : 0;
    if (t == SCAN_B - 1) sh_total = s;
    __syncthreads();
    int total = sh_total;

    if (wid == 0) {
        if (lane == 0) {
            unsigned long long pub = (bid == 0)
                ? ((2ULL << 62) | (unsigned)total)
                : ((1ULL << 62) | (unsigned)total);
            atomicExch(&g_state[bid], pub);
        }
        __syncwarp();
        unsigned running = 0;
        if (bid > 0) {
            int idx = bid - 1;
            while (true) {
                int look = idx - lane;
                unsigned long long st = 0;
                if (look >= 0) {
                    do { st = atomicAdd(&g_state[look], 0ULL); }
                    while ((st >> 62) == 0);
                }
                unsigned flag = (unsigned)(st >> 62);
                unsigned val = (unsigned)(st & 0xffffffffu);
                unsigned mask_inc = __ballot_sync(0xffffffffu, look >= 0 && flag == 2u);
                if (mask_inc) {
                    int firstInc = __ffs(mask_inc) - 1;
                    unsigned c = (look >= 0 && lane <= firstInc) ? val : 0;
                    #pragma unroll
                    for (int o = 16; o > 0; o >>= 1) c += __shfl_down_sync(0xffffffffu, c, o);
                    running += __shfl_sync(0xffffffffu, c, 0);
                    break;
                } else {
                    unsigned c = (look >= 0) ? val : 0;
                    #pragma unroll
                    for (int o = 16; o > 0; o >>= 1) c += __shfl_down_sync(0xffffffffu, c, o);
                    running += __shfl_sync(0xffffffffu, c, 0);
                    idx -= 32;
                    if (idx < 0) break;
                }
            }
            if (lane == 0)
                atomicExch(&g_state[bid], (2ULL << 62) | (unsigned)(running + total));
        }
        if (lane == 0) sh_excl = running;
    }
    __syncthreads();
    int excl = (int)sh_excl;

    if (g < N) g_rs[g] = excl + s - v;     // exclusive global prefix
}

// ---- bucket edges: pos = rs[d] + rank[e]; NO atomics. 4 edges/thread ----
__global__ void k_reorder(const int* __restrict__ ei, const float* __restrict__ ew) {
    int t = blockIdx.x * blockDim.x + threadIdx.x;
    int e = t * 4;
    if (e >= E) return;
    int4   s4 = *((const int4*)(ei + e));
    int4   d4 = *((const int4*)(ei + E + e));
    float4 w4 = *((const float4*)(ew + e));
    int4   r4 = *((const int4*)(g_rank + e));
    #pragma unroll
    for (int k = 0; k < 4; k++) {
        int s = (&s4.x)[k];
        int d = (&d4.x)[k];
        if ((unsigned)s >= (unsigned)N) s = 0;
        if ((unsigned)d >= (unsigned)N) d = 0;
        float wp = (&w4.x)[k] * __ldg(&g_dinv[s]);
        int pos = __ldg(&g_rs[d]) + (&r4.x)[k];
        g_edge[pos] = make_int2(s, __float_as_int(wp));
    }
}

// ---- layer-1 GEMM: y1 = x @ W1 (raw, fp16 out). Independent of prep chain. ----
__global__ void __launch_bounds__(128) k_gemm1(const float* __restrict__ X,
                                               const float* __restrict__ W) {
    constexpr int TX = 16, NPB = 32;
    __shared__ float Ws[64 * 64];
    __shared__ float Xs[NPB][68];
    int tid = threadIdx.y * TX + threadIdx.x;
    {
        const float4* Wg = (const float4*)W;
        float4* Ws4 = (float4*)Ws;
        #pragma unroll
        for (int i = tid; i < 64 * 64 / 4; i += 128) Ws4[i] = Wg[i];
    }
    int nb = blockIdx.x * NPB;                 // N % 32 == 0
    #pragma unroll
    for (int i = tid; i < NPB * 16; i += 128) {
        int node = i >> 4, k4 = i & 15;
        *((float4*)&Xs[node][k4 * 4]) = ((const float4*)(X + (nb + node) * 64))[k4];
    }
    __syncthreads();

    int tx = threadIdx.x, ty = threadIdx.y;    // ty in 0..7
    float4 a0 = {0,0,0,0}, a1 = {0,0,0,0}, a2 = {0,0,0,0}, a3 = {0,0,0,0};
    #pragma unroll
    for (int k4 = 0; k4 < 16; k4++) {
        float4 xv0 = *((const float4*)&Xs[ty][k4 * 4]);
        float4 xv1 = *((const float4*)&Xs[ty + 8][k4 * 4]);
        float4 xv2 = *((const float4*)&Xs[ty + 16][k4 * 4]);
        float4 xv3 = *((const float4*)&Xs[ty + 24][k4 * 4]);
        #pragma unroll
        for (int kk = 0; kk < 4; kk++) {
            float4 w4 = *((const float4*)&Ws[(k4 * 4 + kk) * 64 + tx * 4]);
            float x0 = (&xv0.x)[kk], x1 = (&xv1.x)[kk];
            float x2 = (&xv2.x)[kk], x3 = (&xv3.x)[kk];
            a0.x = fmaf(x0, w4.x, a0.x); a0.y = fmaf(x0, w4.y, a0.y);
            a0.z = fmaf(x0, w4.z, a0.z); a0.w = fmaf(x0, w4.w, a0.w);
            a1.x = fmaf(x1, w4.x, a1.x); a1.y = fmaf(x1, w4.y, a1.y);
            a1.z = fmaf(x1, w4.z, a1.z); a1.w = fmaf(x1, w4.w, a1.w);
            a2.x = fmaf(x2, w4.x, a2.x); a2.y = fmaf(x2, w4.y, a2.y);
            a2.z = fmaf(x2, w4.z, a2.z); a2.w = fmaf(x2, w4.w, a2.w);
            a3.x = fmaf(x3, w4.x, a3.x); a3.y = fmaf(x3, w4.y, a3.y);
            a3.z = fmaf(x3, w4.z, a3.z); a3.w = fmaf(x3, w4.w, a3.w);
        }
    }
    #pragma unroll
    for (int m = 0; m < 4; m++) {
        int n = nb + ty + 8 * m;
        float4 a = (m == 0) ? a0 : (m == 1) ? a1 : (m == 2) ? a2 : a3;
        *((__half2*)&g_y1h[n * 32 + tx * 2])     = __floats2half2_rn(a.x, a.y);
        *((__half2*)&g_y1h[n * 32 + tx * 2 + 1]) = __floats2half2_rn(a.z, a.w);
    }
}

// ---- layer-1 aggregate (warp per node), y1 gathered in fp16, 8-wide pipeline ----
__global__ void __launch_bounds__(256) k_agg1(const float* __restrict__ b1) {
    int warp = (blockIdx.x * 256 + threadIdx.x) >> 5;
    if (warp >= N) return;
    int lane = threadIdx.x & 31;
    int d = warp;
    int beg = g_rs[d], end = beg + g_cnt[d];
    float di = g_dinv[d];
    float2 self = __half22float2(g_y1h[d * 32 + lane]);
    float2 acc;
    acc.x = di * self.x; acc.y = di * self.y;
    int j = beg;
    for (; j + 7 < end; j += 8) {
        int2 e0 = __ldg(&g_edge[j]),     e1 = __ldg(&g_edge[j + 1]);
        int2 e2 = __ldg(&g_edge[j + 2]), e3 = __ldg(&g_edge[j + 3]);
        int2 e4 = __ldg(&g_edge[j + 4]), e5 = __ldg(&g_edge[j + 5]);
        int2 e6 = __ldg(&g_edge[j + 6]), e7 = __ldg(&g_edge[j + 7]);
        float2 v0 = __half22float2(__ldg(&g_y1h[e0.x * 32 + lane]));
        float2 v1 = __half22float2(__ldg(&g_y1h[e1.x * 32 + lane]));
        float2 v2 = __half22float2(__ldg(&g_y1h[e2.x * 32 + lane]));
        float2 v3 = __half22float2(__ldg(&g_y1h[e3.x * 32 + lane]));
        float2 v4 = __half22float2(__ldg(&g_y1h[e4.x * 32 + lane]));
        float2 v5 = __half22float2(__ldg(&g_y1h[e5.x * 32 + lane]));
        float2 v6 = __half22float2(__ldg(&g_y1h[e6.x * 32 + lane]));
        float2 v7 = __half22float2(__ldg(&g_y1h[e7.x * 32 + lane]));
        float w0 = __int_as_float(e0.y), w1 = __int_as_float(e1.y);
        float w2 = __int_as_float(e2.y), w3 = __int_as_float(e3.y);
        float w4 = __int_as_float(e4.y), w5 = __int_as_float(e5.y);
        float w6 = __int_as_float(e6.y), w7 = __int_as_float(e7.y);
        acc.x = fmaf(w0, v0.x, acc.x); acc.y = fmaf(w0, v0.y, acc.y);
        acc.x = fmaf(w1, v1.x, acc.x); acc.y = fmaf(w1, v1.y, acc.y);
        acc.x = fmaf(w2, v2.x, acc.x); acc.y = fmaf(w2, v2.y, acc.y);
        acc.x = fmaf(w3, v3.x, acc.x); acc.y = fmaf(w3, v3.y, acc.y);
        acc.x = fmaf(w4, v4.x, acc.x); acc.y = fmaf(w4, v4.y, acc.y);
        acc.x = fmaf(w5, v5.x, acc.x); acc.y = fmaf(w5, v5.y, acc.y);
        acc.x = fmaf(w6, v6.x, acc.x); acc.y = fmaf(w6, v6.y, acc.y);
        acc.x = fmaf(w7, v7.x, acc.x); acc.y = fmaf(w7, v7.y, acc.y);
    }
    for (; j < end; j++) {
        int2 e = __ldg(&g_edge[j]);
        float w = __int_as_float(e.y);
        float2 v = __half22float2(__ldg(&g_y1h[e.x * 32 + lane]));
        acc.x = fmaf(w, v.x, acc.x); acc.y = fmaf(w, v.y, acc.y);
    }
    float2 h;
    h.x = fmaxf(fmaf(di, acc.x, __ldg(&b1[lane * 2])), 0.0f);
    h.y = fmaxf(fmaf(di, acc.y, __ldg(&b1[lane * 2 + 1])), 0.0f);
    *((float2*)&g_h[d * 64 + lane * 2]) = h;
}

// ---- layer-2 GEMM: y2 = h @ W2 (raw, fp16 out) ----
__global__ void __launch_bounds__(128) k_gemm2(const float* __restrict__ W2) {
    constexpr int TX = 8, TY = 16, NPB = 32;
    __shared__ float Ws[64 * 32];
    __shared__ float Xs[NPB][68];
    int tid = threadIdx.y * TX + threadIdx.x;
    {
        const float4* Wg = (const float4*)W2;
        float4* Ws4 = (float4*)Ws;
        #pragma unroll
        for (int i = tid; i < 64 * 32 / 4; i += 128) Ws4[i] = Wg[i];
    }
    int nb = blockIdx.x * NPB;
    #pragma unroll
    for (int i = tid; i < NPB * 16; i += 128) {
        int node = i >> 4, k4 = i & 15;
        *((float4*)&Xs[node][k4 * 4]) = ((const float4*)&g_h[(nb + node) * 64])[k4];
    }
    __syncthreads();

    int tx = threadIdx.x, ty = threadIdx.y;
    float4 a0 = {0,0,0,0}, a1 = {0,0,0,0};
    #pragma unroll
    for (int k = 0; k < 64; k++) {
        float4 w4 = *((const float4*)&Ws[k * 32 + tx * 4]);
        float x0 = Xs[ty][k], x1 = Xs[ty + TY][k];
        a0.x = fmaf(x0, w4.x, a0.x); a0.y = fmaf(x0, w4.y, a0.y);
        a0.z = fmaf(x0, w4.z, a0.z); a0.w = fmaf(x0, w4.w, a0.w);
        a1.x = fmaf(x1, w4.x, a1.x); a1.y = fmaf(x1, w4.y, a1.y);
        a1.z = fmaf(x1, w4.z, a1.z); a1.w = fmaf(x1, w4.w, a1.w);
    }
    int n0 = nb + ty, n1 = nb + ty + TY;
    *((__half2*)&g_y2h[n0 * 16 + tx * 2])     = __floats2half2_rn(a0.x, a0.y);
    *((__half2*)&g_y2h[n0 * 16 + tx * 2 + 1]) = __floats2half2_rn(a0.z, a0.w);
    *((__half2*)&g_y2h[n1 * 16 + tx * 2])     = __floats2half2_rn(a1.x, a1.y);
    *((__half2*)&g_y2h[n1 * 16 + tx * 2 + 1]) = __floats2half2_rn(a1.z, a1.w);
}

// ---- layer-2 aggregate + epilogue, y2 gathered in fp16, 8-wide pipeline ----
__global__ void __launch_bounds__(256) k_agg2(const float* __restrict__ b2,
                                              float* __restrict__ out) {
    const __half* y2 = (const __half*)g_y2h;
    int warp = (blockIdx.x * 256 + threadIdx.x) >> 5;
    if (warp >= N) return;
    int lane = threadIdx.x & 31;
    int d = warp;
    int beg = g_rs[d], end = beg + g_cnt[d];
    float di = g_dinv[d];
    float acc = di * __half2float(y2[d * 32 + lane]);   // self loop
    int j = beg;
    for (; j + 7 < end; j += 8) {
        int2 e0 = __ldg(&g_edge[j]),     e1 = __ldg(&g_edge[j + 1]);
        int2 e2 = __ldg(&g_edge[j + 2]), e3 = __ldg(&g_edge[j + 3]);
        int2 e4 = __ldg(&g_edge[j + 4]), e5 = __ldg(&g_edge[j + 5]);
        int2 e6 = __ldg(&g_edge[j + 6]), e7 = __ldg(&g_edge[j + 7]);
        float v0 = __half2float(__ldg(&y2[e0.x * 32 + lane]));
        float v1 = __half2float(__ldg(&y2[e1.x * 32 + lane]));
        float v2 = __half2float(__ldg(&y2[e2.x * 32 + lane]));
        float v3 = __half2float(__ldg(&y2[e3.x * 32 + lane]));
        float v4 = __half2float(__ldg(&y2[e4.x * 32 + lane]));
        float v5 = __half2float(__ldg(&y2[e5.x * 32 + lane]));
        float v6 = __half2float(__ldg(&y2[e6.x * 32 + lane]));
        float v7 = __half2float(__ldg(&y2[e7.x * 32 + lane]));
        acc = fmaf(__int_as_float(e0.y), v0, acc);
        acc = fmaf(__int_as_float(e1.y), v1, acc);
        acc = fmaf(__int_as_float(e2.y), v2, acc);
        acc = fmaf(__int_as_float(e3.y), v3, acc);
        acc = fmaf(__int_as_float(e4.y), v4, acc);
        acc = fmaf(__int_as_float(e5.y), v5, acc);
        acc = fmaf(__int_as_float(e6.y), v6, acc);
        acc = fmaf(__int_as_float(e7.y), v7, acc);
    }
    for (; j < end; j++) {
        int2 e = __ldg(&g_edge[j]);
        acc = fmaf(__int_as_float(e.y), __half2float(__ldg(&y2[e.x * 32 + lane])), acc);
    }
    out[d * 32 + lane] = fmaf(di, acc, b2[lane]);
}

extern "C" void kernel_launch(void* const* d_in, const int* in_sizes, int n_in,
                              void* d_out, int out_size) {
    const float* x  = (const float*)d_in[0];
    const int*   ei = (const int*)d_in[1];     // edge_index as int32
    const float* ew = (const float*)d_in[2];
    const float* W1 = (const float*)d_in[3];
    const float* b1 = (const float*)d_in[4];
    const float* W2 = (const float*)d_in[5];
    const float* b2 = (const float*)d_in[6];
    float* out = (float*)d_out;

    // side stream for gemm1 (independent of the prep chain)
    cudaStream_t s2;
    cudaStreamCreateWithFlags(&s2, cudaStreamNonBlocking);
    cudaEvent_t ev_fork, ev_join;
    cudaEventCreateWithFlags(&ev_fork, cudaEventDisableTiming);
    cudaEventCreateWithFlags(&ev_join, cudaEventDisableTiming);

    cudaEventRecord(ev_fork, 0);
    cudaStreamWaitEvent(s2, ev_fork, 0);
    k_gemm1<<<N / 32, dim3(16, 8), 0, s2>>>(x, W1);
    cudaEventRecord(ev_join, s2);

    // main chain
    void* p_zero = nullptr;
    cudaGetSymbolAddress(&p_zero, g_zero);
    cudaMemsetAsync(p_zero, 0, (N + NB_SCAN + 1) * sizeof(unsigned long long));
    k_prep   <<<(E / 4 + 255) / 256, 256>>>(ei, ew);
    k_scan   <<<NB_SCAN, SCAN_B>>>();
    k_reorder<<<(E / 4 + 255) / 256, 256>>>(ei, ew);

    cudaStreamWaitEvent(0, ev_join, 0);
    k_agg1   <<<(N * 32 + 255) / 256, 256>>>(b1);
    k_gemm2  <<<N / 32, dim3(8, 16)>>>(W2);
    k_agg2   <<<(N * 32 + 255) / 256, 256>>>(b2, out);
}

// round 12
// speedup vs baseline: 1.0545x; 1.0545x over previous
#include <cuda_runtime.h>
#include <cuda_fp16.h>

static constexpr int N = 100000;
static constexpr int E = 1600000;
static constexpr int SCAN_B = 512;
static constexpr int NB_SCAN = (N + SCAN_B - 1) / SCAN_B;   // 196

// ---- zeroed-per-launch region (single memset): g_cw[N] | g_state[NB] | ticket ----
__device__ unsigned long long g_zero[N + NB_SCAN + 1];
#define g_cw     (g_zero)                  // packed: count<<40 | wdeg*2^24
#define g_state  (g_zero + N)              // lookback: flag<<62 | inclusive/aggregate
#define g_ticket (g_zero + N + NB_SCAN)

__device__ float    g_dinv[N];
__device__ int      g_cnt[N];
__device__ int      g_rs[N];
__device__ int      g_cur[N];
__device__ unsigned g_edge[E];             // packed: src<<15 | fp16bits(w*dinv[src])
__device__ __half2  g_y1h[N * 32];         // x @ W1, raw, fp16 (128 B/row)
__device__ float    g_h [N * 64];          // relu'd hidden, fp32
__device__ __half2  g_y2h[N * 16];         // h @ W2, raw, fp16 (64 B/row)

// ---- count + weighted degree: fire-and-forget packed u64 atomic (REDG path) ----
__global__ void k_prep(const int* __restrict__ ei, const float* __restrict__ ew) {
    int t = blockIdx.x * blockDim.x + threadIdx.x;
    int e = t * 4;
    if (e >= E) return;
    int4   d4 = *((const int4*)(ei + E + e));
    float4 w4 = *((const float4*)(ew + e));
    #pragma unroll
    for (int k = 0; k < 4; k++) {
        int d = (&d4.x)[k];
        float w = (&w4.x)[k];
        if ((unsigned)d >= (unsigned)N) d = 0;
        unsigned long long v = (1ULL << 40) |
            (unsigned long long)(unsigned int)__float2uint_rn(w * 16777216.0f);
        atomicAdd(&g_cw[d], v);            // result unused -> REDG
    }
}

// ---- single-kernel scan: decode + decoupled-lookback prefix + rs/cur/dinv ----
__global__ void __launch_bounds__(SCAN_B) k_scan() {
    __shared__ int wsum[16];
    __shared__ int sh_bid;
    __shared__ unsigned sh_excl;
    __shared__ int sh_total;
    int t = threadIdx.x, lane = t & 31, wid = t >> 5;

    if (t == 0) sh_bid = (int)atomicAdd(g_ticket, 1ULL);   // ordered tile id
    __syncthreads();
    int bid = sh_bid;
    int g = bid * SCAN_B + t;

    int v = 0;
    if (g < N) {
        unsigned long long p = g_cw[g];
        v = (int)(p >> 40);
        float wdeg = (float)(p & ((1ULL << 40) - 1)) * (1.0f / 16777216.0f);
        g_cnt[g] = v;
        g_dinv[g] = rsqrtf(1.0f + wdeg);
    }
    int s = v;
    #pragma unroll
    for (int o = 1; o < 32; o <<= 1) {
        int n = __shfl_up_sync(0xffffffffu, s, o);
        if (lane >= o) s += n;
    }
    if (lane == 31) wsum[wid] = s;
    __syncthreads();
    if (wid == 0) {
        int ws = (lane < 16) ? wsum[lane] : 0;
        #pragma unroll
        for (int o = 1; o < 16; o <<= 1) {
            int n = __shfl_up_sync(0xffffffffu, ws, o);
            if (lane >= o) ws += n;
        }
        if (lane < 16) wsum[lane] = ws;
    }
    __syncthreads();
    s += wid ? wsum[wid - 1] : 0;
    if (t == SCAN_B - 1) sh_total = s;
    __syncthreads();
    int total = sh_total;

    if (wid == 0) {
        if (lane == 0) {
            unsigned long long pub = (bid == 0)
                ? ((2ULL << 62) | (unsigned)total)
                : ((1ULL << 62) | (unsigned)total);
            atomicExch(&g_state[bid], pub);
        }
        __syncwarp();
        unsigned running = 0;
        if (bid > 0) {
            int idx = bid - 1;
            while (true) {
                int look = idx - lane;
                unsigned long long st = 0;
                if (look >= 0) {
                    do { st = atomicAdd(&g_state[look], 0ULL); }
                    while ((st >> 62) == 0);
                }
                unsigned flag = (unsigned)(st >> 62);
                unsigned val = (unsigned)(st & 0xffffffffu);
                unsigned mask_inc = __ballot_sync(0xffffffffu, look >= 0 && flag == 2u);
                if (mask_inc) {
                    int firstInc = __ffs(mask_inc) - 1;
                    unsigned c = (look >= 0 && lane <= firstInc) ? val : 0;
                    #pragma unroll
                    for (int o = 16; o > 0; o >>= 1) c += __shfl_down_sync(0xffffffffu, c, o);
                    running += __shfl_sync(0xffffffffu, c, 0);
                    break;
                } else {
                    unsigned c = (look >= 0) ? val : 0;
                    #pragma unroll
                    for (int o = 16; o > 0; o >>= 1) c += __shfl_down_sync(0xffffffffu, c, o);
                    running += __shfl_sync(0xffffffffu, c, 0);
                    idx -= 32;
                    if (idx < 0) break;
                }
            }
            if (lane == 0)
                atomicExch(&g_state[bid], (2ULL << 62) | (unsigned)(running + total));
        }
        if (lane == 0) sh_excl = running;
    }
    __syncthreads();
    int excl = (int)sh_excl;

    if (g < N) {
        int start = excl + s - v;
        g_rs[g]  = start;
        g_cur[g] = start;
    }
}

// ---- bucket edges by destination (cursor atomic), packed 4-byte record ----
__global__ void k_reorder(const int* __restrict__ ei, const float* __restrict__ ew) {
    int e = blockIdx.x * blockDim.x + threadIdx.x;
    if (e >= E) return;
    int s = ei[e];
    int d = ei[E + e];
    if ((unsigned)s >= (unsigned)N) s = 0;
    if ((unsigned)d >= (unsigned)N) d = 0;
    float wp = ew[e] * __ldg(&g_dinv[s]);              // >= 0 -> fp16 sign bit free
    unsigned hb = (unsigned)__half_as_ushort(__float2half_rn(wp));
    unsigned packed = ((unsigned)s << 15) | (hb & 0x7fffu);
    int pos = atomicAdd(&g_cur[d], 1);
    g_edge[pos] = packed;
}

__device__ __forceinline__ float unpack_w(unsigned p) {
    return __half2float(__ushort_as_half((unsigned short)(p & 0x7fffu)));
}

// ---- layer-1 GEMM: y1 = x @ W1 (raw, fp16 out). Independent of prep chain. ----
__global__ void __launch_bounds__(128) k_gemm1(const float* __restrict__ X,
                                               const float* __restrict__ W) {
    constexpr int TX = 16, NPB = 32;
    __shared__ float Ws[64 * 64];
    __shared__ float Xs[NPB][68];
    int tid = threadIdx.y * TX + threadIdx.x;
    {
        const float4* Wg = (const float4*)W;
        float4* Ws4 = (float4*)Ws;
        #pragma unroll
        for (int i = tid; i < 64 * 64 / 4; i += 128) Ws4[i] = Wg[i];
    }
    int nb = blockIdx.x * NPB;                 // N % 32 == 0
    #pragma unroll
    for (int i = tid; i < NPB * 16; i += 128) {
        int node = i >> 4, k4 = i & 15;
        *((float4*)&Xs[node][k4 * 4]) = ((const float4*)(X + (nb + node) * 64))[k4];
    }
    __syncthreads();

    int tx = threadIdx.x, ty = threadIdx.y;    // ty in 0..7
    float4 a0 = {0,0,0,0}, a1 = {0,0,0,0}, a2 = {0,0,0,0}, a3 = {0,0,0,0};
    #pragma unroll
    for (int k4 = 0; k4 < 16; k4++) {
        float4 xv0 = *((const float4*)&Xs[ty][k4 * 4]);
        float4 xv1 = *((const float4*)&Xs[ty + 8][k4 * 4]);
        float4 xv2 = *((const float4*)&Xs[ty + 16][k4 * 4]);
        float4 xv3 = *((const float4*)&Xs[ty + 24][k4 * 4]);
        #pragma unroll
        for (int kk = 0; kk < 4; kk++) {
            float4 w4 = *((const float4*)&Ws[(k4 * 4 + kk) * 64 + tx * 4]);
            float x0 = (&xv0.x)[kk], x1 = (&xv1.x)[kk];
            float x2 = (&xv2.x)[kk], x3 = (&xv3.x)[kk];
            a0.x = fmaf(x0, w4.x, a0.x); a0.y = fmaf(x0, w4.y, a0.y);
            a0.z = fmaf(x0, w4.z, a0.z); a0.w = fmaf(x0, w4.w, a0.w);
            a1.x = fmaf(x1, w4.x, a1.x); a1.y = fmaf(x1, w4.y, a1.y);
            a1.z = fmaf(x1, w4.z, a1.z); a1.w = fmaf(x1, w4.w, a1.w);
            a2.x = fmaf(x2, w4.x, a2.x); a2.y = fmaf(x2, w4.y, a2.y);
            a2.z = fmaf(x2, w4.z, a2.z); a2.w = fmaf(x2, w4.w, a2.w);
            a3.x = fmaf(x3, w4.x, a3.x); a3.y = fmaf(x3, w4.y, a3.y);
            a3.z = fmaf(x3, w4.z, a3.z); a3.w = fmaf(x3, w4.w, a3.w);
        }
    }
    #pragma unroll
    for (int m = 0; m < 4; m++) {
        int n = nb + ty + 8 * m;
        float4 a = (m == 0) ? a0 : (m == 1) ? a1 : (m == 2) ? a2 : a3;
        *((__half2*)&g_y1h[n * 32 + tx * 2])     = __floats2half2_rn(a.x, a.y);
        *((__half2*)&g_y1h[n * 32 + tx * 2 + 1]) = __floats2half2_rn(a.z, a.w);
    }
}

// ---- layer-1 aggregate (warp per node), fp16 gathers, packed edges ----
__global__ void __launch_bounds__(256) k_agg1(const float* __restrict__ b1) {
    int warp = (blockIdx.x * 256 + threadIdx.x) >> 5;
    if (warp >= N) return;
    int lane = threadIdx.x & 31;
    int d = warp;
    int beg = g_rs[d], end = beg + g_cnt[d];
    float di = g_dinv[d];
    float2 self = __half22float2(g_y1h[d * 32 + lane]);
    float2 acc;
    acc.x = di * self.x; acc.y = di * self.y;
    int j = beg;
    for (; j + 3 < end; j += 4) {
        unsigned p0 = __ldg(&g_edge[j]),     p1 = __ldg(&g_edge[j + 1]);
        unsigned p2 = __ldg(&g_edge[j + 2]), p3 = __ldg(&g_edge[j + 3]);
        float2 v0 = __half22float2(__ldg(&g_y1h[(p0 >> 15) * 32 + lane]));
        float2 v1 = __half22float2(__ldg(&g_y1h[(p1 >> 15) * 32 + lane]));
        float2 v2 = __half22float2(__ldg(&g_y1h[(p2 >> 15) * 32 + lane]));
        float2 v3 = __half22float2(__ldg(&g_y1h[(p3 >> 15) * 32 + lane]));
        float w0 = unpack_w(p0), w1 = unpack_w(p1);
        float w2 = unpack_w(p2), w3 = unpack_w(p3);
        acc.x = fmaf(w0, v0.x, acc.x); acc.y = fmaf(w0, v0.y, acc.y);
        acc.x = fmaf(w1, v1.x, acc.x); acc.y = fmaf(w1, v1.y, acc.y);
        acc.x = fmaf(w2, v2.x, acc.x); acc.y = fmaf(w2, v2.y, acc.y);
        acc.x = fmaf(w3, v3.x, acc.x); acc.y = fmaf(w3, v3.y, acc.y);
    }
    for (; j < end; j++) {
        unsigned p = __ldg(&g_edge[j]);
        float w = unpack_w(p);
        float2 v = __half22float2(__ldg(&g_y1h[(p >> 15) * 32 + lane]));
        acc.x = fmaf(w, v.x, acc.x); acc.y = fmaf(w, v.y, acc.y);
    }
    float2 h;
    h.x = fmaxf(fmaf(di, acc.x, __ldg(&b1[lane * 2])), 0.0f);
    h.y = fmaxf(fmaf(di, acc.y, __ldg(&b1[lane * 2 + 1])), 0.0f);
    *((float2*)&g_h[d * 64 + lane * 2]) = h;
}

// ---- layer-2 GEMM: y2 = h @ W2 (raw, fp16 out) ----
__global__ void __launch_bounds__(128) k_gemm2(const float* __restrict__ W2) {
    constexpr int TX = 8, TY = 16, NPB = 32;
    __shared__ float Ws[64 * 32];
    __shared__ float Xs[NPB][68];
    int tid = threadIdx.y * TX + threadIdx.x;
    {
        const float4* Wg = (const float4*)W2;
        float4* Ws4 = (float4*)Ws;
        #pragma unroll
        for (int i = tid; i < 64 * 32 / 4; i += 128) Ws4[i] = Wg[i];
    }
    int nb = blockIdx.x * NPB;
    #pragma unroll
    for (int i = tid; i < NPB * 16; i += 128) {
        int node = i >> 4, k4 = i & 15;
        *((float4*)&Xs[node][k4 * 4]) = ((const float4*)&g_h[(nb + node) * 64])[k4];
    }
    __syncthreads();

    int tx = threadIdx.x, ty = threadIdx.y;
    float4 a0 = {0,0,0,0}, a1 = {0,0,0,0};
    #pragma unroll
    for (int k = 0; k < 64; k++) {
        float4 w4 = *((const float4*)&Ws[k * 32 + tx * 4]);
        float x0 = Xs[ty][k], x1 = Xs[ty + TY][k];
        a0.x = fmaf(x0, w4.x, a0.x); a0.y = fmaf(x0, w4.y, a0.y);
        a0.z = fmaf(x0, w4.z, a0.z); a0.w = fmaf(x0, w4.w, a0.w);
        a1.x = fmaf(x1, w4.x, a1.x); a1.y = fmaf(x1, w4.y, a1.y);
        a1.z = fmaf(x1, w4.z, a1.z); a1.w = fmaf(x1, w4.w, a1.w);
    }
    int n0 = nb + ty, n1 = nb + ty + TY;
    *((__half2*)&g_y2h[n0 * 16 + tx * 2])     = __floats2half2_rn(a0.x, a0.y);
    *((__half2*)&g_y2h[n0 * 16 + tx * 2 + 1]) = __floats2half2_rn(a0.z, a0.w);
    *((__half2*)&g_y2h[n1 * 16 + tx * 2])     = __floats2half2_rn(a1.x, a1.y);
    *((__half2*)&g_y2h[n1 * 16 + tx * 2 + 1]) = __floats2half2_rn(a1.z, a1.w);
}

// ---- layer-2 aggregate + epilogue, fp16 gathers, packed edges ----
__global__ void __launch_bounds__(256) k_agg2(const float* __restrict__ b2,
                                              float* __restrict__ out) {
    const __half* y2 = (const __half*)g_y2h;
    int warp = (blockIdx.x * 256 + threadIdx.x) >> 5;
    if (warp >= N) return;
    int lane = threadIdx.x & 31;
    int d = warp;
    int beg = g_rs[d], end = beg + g_cnt[d];
    float di = g_dinv[d];
    float acc = di * __half2float(y2[d * 32 + lane]);   // self loop
    int j = beg;
    for (; j + 3 < end; j += 4) {
        unsigned p0 = __ldg(&g_edge[j]),     p1 = __ldg(&g_edge[j + 1]);
        unsigned p2 = __ldg(&g_edge[j + 2]), p3 = __ldg(&g_edge[j + 3]);
        float v0 = __half2float(__ldg(&y2[(p0 >> 15) * 32 + lane]));
        float v1 = __half2float(__ldg(&y2[(p1 >> 15) * 32 + lane]));
        float v2 = __half2float(__ldg(&y2[(p2 >> 15) * 32 + lane]));
        float v3 = __half2float(__ldg(&y2[(p3 >> 15) * 32 + lane]));
        acc = fmaf(unpack_w(p0), v0, acc);
        acc = fmaf(unpack_w(p1), v1, acc);
        acc = fmaf(unpack_w(p2), v2, acc);
        acc = fmaf(unpack_w(p3), v3, acc);
    }
    for (; j < end; j++) {
        unsigned p = __ldg(&g_edge[j]);
        acc = fmaf(unpack_w(p), __half2float(__ldg(&y2[(p >> 15) * 32 + lane])), acc);
    }
    out[d * 32 + lane] = fmaf(di, acc, b2[lane]);
}

extern "C" void kernel_launch(void* const* d_in, const int* in_sizes, int n_in,
                              void* d_out, int out_size) {
    const float* x  = (const float*)d_in[0];
    const int*   ei = (const int*)d_in[1];     // edge_index as int32
    const float* ew = (const float*)d_in[2];
    const float* W1 = (const float*)d_in[3];
    const float* b1 = (const float*)d_in[4];
    const float* W2 = (const float*)d_in[5];
    const float* b2 = (const float*)d_in[6];
    float* out = (float*)d_out;

    // side stream for gemm1 (independent of the prep chain)
    cudaStream_t s2;
    cudaStreamCreateWithFlags(&s2, cudaStreamNonBlocking);
    cudaEvent_t ev_fork, ev_join;
    cudaEventCreateWithFlags(&ev_fork, cudaEventDisableTiming);
    cudaEventCreateWithFlags(&ev_join, cudaEventDisableTiming);

    cudaEventRecord(ev_fork, 0);
    cudaStreamWaitEvent(s2, ev_fork, 0);
    k_gemm1<<<N / 32, dim3(16, 8), 0, s2>>>(x, W1);
    cudaEventRecord(ev_join, s2);

    // main chain
    void* p_zero = nullptr;
    cudaGetSymbolAddress(&p_zero, g_zero);
    cudaMemsetAsync(p_zero, 0, (N + NB_SCAN + 1) * sizeof(unsigned long long));
    k_prep   <<<(E / 4 + 255) / 256, 256>>>(ei, ew);
    k_scan   <<<NB_SCAN, SCAN_B>>>();
    k_reorder<<<(E + 255) / 256, 256>>>(ei, ew);

    cudaStreamWaitEvent(0, ev_join, 0);
    k_agg1   <<<(N * 32 + 255) / 256, 256>>>(b1);
    k_gemm2  <<<N / 32, dim3(8, 16)>>>(W2);
    k_agg2   <<<(N * 32 + 255) / 256, 256>>>(b2, out);
}

// round 13
// speedup vs baseline: 1.0718x; 1.0164x over previous
#include <cuda_runtime.h>
#include <cuda_fp16.h>

static constexpr int N = 100000;
static constexpr int E = 1600000;
static constexpr int SCAN_B = 512;
static constexpr int NB_SCAN = (N + SCAN_B - 1) / SCAN_B;   // 196

// ---- zeroed-per-launch region (single memset): g_cw[N] | g_state[NB] | ticket ----
__device__ unsigned long long g_zero[N + NB_SCAN + 1];
#define g_cw     (g_zero)                  // packed: count<<40 | wdeg*2^24
#define g_state  (g_zero + N)              // lookback: flag<<62 | inclusive/aggregate
#define g_ticket (g_zero + N + NB_SCAN)

__device__ float    g_dinv[N];
__device__ int      g_cnt[N];
__device__ int      g_rs[N];
__device__ int      g_cur[N];
__device__ unsigned g_edge[E];             // packed: src<<15 | fp16bits(w*dinv[src])
__device__ __half2  g_y1h[N * 32];         // x @ W1, raw, fp16 (128 B/row)
__device__ float    g_h [N * 64];          // relu'd hidden, fp32
__device__ __half2  g_y2h[N * 16];         // h @ W2, raw, fp16 (64 B/row)

// ---- count + weighted degree: fire-and-forget packed u64 atomic (REDG path) ----
__global__ void k_prep(const int* __restrict__ ei, const float* __restrict__ ew) {
    int t = blockIdx.x * blockDim.x + threadIdx.x;
    int e = t * 4;
    if (e >= E) return;
    int4   d4 = *((const int4*)(ei + E + e));
    float4 w4 = *((const float4*)(ew + e));
    #pragma unroll
    for (int k = 0; k < 4; k++) {
        int d = (&d4.x)[k];
        float w = (&w4.x)[k];
        if ((unsigned)d >= (unsigned)N) d = 0;
        unsigned long long v = (1ULL << 40) |
            (unsigned long long)(unsigned int)__float2uint_rn(w * 16777216.0f);
        atomicAdd(&g_cw[d], v);            // result unused -> REDG
    }
}

// ---- single-kernel scan: decode + decoupled-lookback prefix + rs/cur/dinv ----
__global__ void __launch_bounds__(SCAN_B) k_scan() {
    __shared__ int wsum[16];
    __shared__ int sh_bid;
    __shared__ unsigned sh_excl;
    __shared__ int sh_total;
    int t = threadIdx.x, lane = t & 31, wid = t >> 5;

    if (t == 0) sh_bid = (int)atomicAdd(g_ticket, 1ULL);   // ordered tile id
    __syncthreads();
    int bid = sh_bid;
    int g = bid * SCAN_B + t;

    int v = 0;
    if (g < N) {
        unsigned long long p = g_cw[g];
        v = (int)(p >> 40);
        float wdeg = (float)(p & ((1ULL << 40) - 1)) * (1.0f / 16777216.0f);
        g_cnt[g] = v;
        g_dinv[g] = rsqrtf(1.0f + wdeg);
    }
    int s = v;
    #pragma unroll
    for (int o = 1; o < 32; o <<= 1) {
        int n = __shfl_up_sync(0xffffffffu, s, o);
        if (lane >= o) s += n;
    }
    if (lane == 31) wsum[wid] = s;
    __syncthreads();
    if (wid == 0) {
        int ws = (lane < 16) ? wsum[lane] : 0;
        #pragma unroll
        for (int o = 1; o < 16; o <<= 1) {
            int n = __shfl_up_sync(0xffffffffu, ws, o);
            if (lane >= o) ws += n;
        }
        if (lane < 16) wsum[lane] = ws;
    }
    __syncthreads();
    s += wid ? wsum[wid - 1] : 0;
    if (t == SCAN_B - 1) sh_total = s;
    __syncthreads();
    int total = sh_total;

    if (wid == 0) {
        if (lane == 0) {
            unsigned long long pub = (bid == 0)
                ? ((2ULL << 62) | (unsigned)total)
                : ((1ULL << 62) | (unsigned)total);
            atomicExch(&g_state[bid], pub);
        }
        __syncwarp();
        unsigned running = 0;
        if (bid > 0) {
            int idx = bid - 1;
            while (true) {
                int look = idx - lane;
                unsigned long long st = 0;
                if (look >= 0) {
                    do { st = atomicAdd(&g_state[look], 0ULL); }
                    while ((st >> 62) == 0);
                }
                unsigned flag = (unsigned)(st >> 62);
                unsigned val = (unsigned)(st & 0xffffffffu);
                unsigned mask_inc = __ballot_sync(0xffffffffu, look >= 0 && flag == 2u);
                if (mask_inc) {
                    int firstInc = __ffs(mask_inc) - 1;
                    unsigned c = (look >= 0 && lane <= firstInc) ? val : 0;
                    #pragma unroll
                    for (int o = 16; o > 0; o >>= 1) c += __shfl_down_sync(0xffffffffu, c, o);
                    running += __shfl_sync(0xffffffffu, c, 0);
                    break;
                } else {
                    unsigned c = (look >= 0) ? val : 0;
                    #pragma unroll
                    for (int o = 16; o > 0; o >>= 1) c += __shfl_down_sync(0xffffffffu, c, o);
                    running += __shfl_sync(0xffffffffu, c, 0);
                    idx -= 32;
                    if (idx < 0) break;
                }
            }
            if (lane == 0)
                atomicExch(&g_state[bid], (2ULL << 62) | (unsigned)(running + total));
        }
        if (lane == 0) sh_excl = running;
    }
    __syncthreads();
    int excl = (int)sh_excl;

    if (g < N) {
        int start = excl + s - v;
        g_rs[g]  = start;
        g_cur[g] = start;
    }
}

// ---- bucket edges (cursor atomic), packed 4B record, 4 edges/thread for ILP ----
__global__ void k_reorder(const int* __restrict__ ei, const float* __restrict__ ew) {
    int t = blockIdx.x * blockDim.x + threadIdx.x;
    int e = t * 4;
    if (e >= E) return;
    int4   s4 = *((const int4*)(ei + e));
    int4   d4 = *((const int4*)(ei + E + e));
    float4 w4 = *((const float4*)(ew + e));
    #pragma unroll
    for (int k = 0; k < 4; k++) {
        int s = (&s4.x)[k];
        int d = (&d4.x)[k];
        if ((unsigned)s >= (unsigned)N) s = 0;
        if ((unsigned)d >= (unsigned)N) d = 0;
        float wp = (&w4.x)[k] * __ldg(&g_dinv[s]);     // >= 0 -> fp16 sign bit free
        unsigned hb = (unsigned)__half_as_ushort(__float2half_rn(wp));
        unsigned packed = ((unsigned)s << 15) | (hb & 0x7fffu);
        int pos = atomicAdd(&g_cur[d], 1);
        g_edge[pos] = packed;
    }
}

__device__ __forceinline__ float unpack_w(unsigned p) {
    return __half2float(__ushort_as_half((unsigned short)(p & 0x7fffu)));
}

// ---- layer-1 GEMM: y1 = x @ W1 (raw, fp16 out). Independent of prep chain. ----
__global__ void __launch_bounds__(128) k_gemm1(const float* __restrict__ X,
                                               const float* __restrict__ W) {
    constexpr int TX = 16, NPB = 32;
    __shared__ float Ws[64 * 64];
    __shared__ float Xs[NPB][68];
    int tid = threadIdx.y * TX + threadIdx.x;
    {
        const float4* Wg = (const float4*)W;
        float4* Ws4 = (float4*)Ws;
        #pragma unroll
        for (int i = tid; i < 64 * 64 / 4; i += 128) Ws4[i] = Wg[i];
    }
    int nb = blockIdx.x * NPB;                 // N % 32 == 0
    #pragma unroll
    for (int i = tid; i < NPB * 16; i += 128) {
        int node = i >> 4, k4 = i & 15;
        *((float4*)&Xs[node][k4 * 4]) = ((const float4*)(X + (nb + node) * 64))[k4];
    }
    __syncthreads();

    int tx = threadIdx.x, ty = threadIdx.y;    // ty in 0..7
    float4 a0 = {0,0,0,0}, a1 = {0,0,0,0}, a2 = {0,0,0,0}, a3 = {0,0,0,0};
    #pragma unroll
    for (int k4 = 0; k4 < 16; k4++) {
        float4 xv0 = *((const float4*)&Xs[ty][k4 * 4]);
        float4 xv1 = *((const float4*)&Xs[ty + 8][k4 * 4]);
        float4 xv2 = *((const float4*)&Xs[ty + 16][k4 * 4]);
        float4 xv3 = *((const float4*)&Xs[ty + 24][k4 * 4]);
        #pragma unroll
        for (int kk = 0; kk < 4; kk++) {
            float4 w4 = *((const float4*)&Ws[(k4 * 4 + kk) * 64 + tx * 4]);
            float x0 = (&xv0.x)[kk], x1 = (&xv1.x)[kk];
            float x2 = (&xv2.x)[kk], x3 = (&xv3.x)[kk];
            a0.x = fmaf(x0, w4.x, a0.x); a0.y = fmaf(x0, w4.y, a0.y);
            a0.z = fmaf(x0, w4.z, a0.z); a0.w = fmaf(x0, w4.w, a0.w);
            a1.x = fmaf(x1, w4.x, a1.x); a1.y = fmaf(x1, w4.y, a1.y);
            a1.z = fmaf(x1, w4.z, a1.z); a1.w = fmaf(x1, w4.w, a1.w);
            a2.x = fmaf(x2, w4.x, a2.x); a2.y = fmaf(x2, w4.y, a2.y);
            a2.z = fmaf(x2, w4.z, a2.z); a2.w = fmaf(x2, w4.w, a2.w);
            a3.x = fmaf(x3, w4.x, a3.x); a3.y = fmaf(x3, w4.y, a3.y);
            a3.z = fmaf(x3, w4.z, a3.z); a3.w = fmaf(x3, w4.w, a3.w);
        }
    }
    #pragma unroll
    for (int m = 0; m < 4; m++) {
        int n = nb + ty + 8 * m;
        float4 a = (m == 0) ? a0 : (m == 1) ? a1 : (m == 2) ? a2 : a3;
        *((__half2*)&g_y1h[n * 32 + tx * 2])     = __floats2half2_rn(a.x, a.y);
        *((__half2*)&g_y1h[n * 32 + tx * 2 + 1]) = __floats2half2_rn(a.z, a.w);
    }
}

// ---- layer-1 aggregate (warp per node), fp16 gathers, packed edges, 8-wide ----
__global__ void __launch_bounds__(256) k_agg1(const float* __restrict__ b1) {
    int warp = (blockIdx.x * 256 + threadIdx.x) >> 5;
    if (warp >= N) return;
    int lane = threadIdx.x & 31;
    int d = warp;
    int beg = g_rs[d], end = beg + g_cnt[d];
    float di = g_dinv[d];
    float2 self = __half22float2(g_y1h[d * 32 + lane]);
    float2 acc;
    acc.x = di * self.x; acc.y = di * self.y;
    int j = beg;
    for (; j + 7 < end; j += 8) {
        unsigned p0 = __ldg(&g_edge[j]),     p1 = __ldg(&g_edge[j + 1]);
        unsigned p2 = __ldg(&g_edge[j + 2]), p3 = __ldg(&g_edge[j + 3]);
        unsigned p4 = __ldg(&g_edge[j + 4]), p5 = __ldg(&g_edge[j + 5]);
        unsigned p6 = __ldg(&g_edge[j + 6]), p7 = __ldg(&g_edge[j + 7]);
        float2 v0 = __half22float2(__ldg(&g_y1h[(p0 >> 15) * 32 + lane]));
        float2 v1 = __half22float2(__ldg(&g_y1h[(p1 >> 15) * 32 + lane]));
        float2 v2 = __half22float2(__ldg(&g_y1h[(p2 >> 15) * 32 + lane]));
        float2 v3 = __half22float2(__ldg(&g_y1h[(p3 >> 15) * 32 + lane]));
        float2 v4 = __half22float2(__ldg(&g_y1h[(p4 >> 15) * 32 + lane]));
        float2 v5 = __half22float2(__ldg(&g_y1h[(p5 >> 15) * 32 + lane]));
        float2 v6 = __half22float2(__ldg(&g_y1h[(p6 >> 15) * 32 + lane]));
        float2 v7 = __half22float2(__ldg(&g_y1h[(p7 >> 15) * 32 + lane]));
        float w0 = unpack_w(p0), w1 = unpack_w(p1);
        float w2 = unpack_w(p2), w3 = unpack_w(p3);
        float w4 = unpack_w(p4), w5 = unpack_w(p5);
        float w6 = unpack_w(p6), w7 = unpack_w(p7);
        acc.x = fmaf(w0, v0.x, acc.x); acc.y = fmaf(w0, v0.y, acc.y);
        acc.x = fmaf(w1, v1.x, acc.x); acc.y = fmaf(w1, v1.y, acc.y);
        acc.x = fmaf(w2, v2.x, acc.x); acc.y = fmaf(w2, v2.y, acc.y);
        acc.x = fmaf(w3, v3.x, acc.x); acc.y = fmaf(w3, v3.y, acc.y);
        acc.x = fmaf(w4, v4.x, acc.x); acc.y = fmaf(w4, v4.y, acc.y);
        acc.x = fmaf(w5, v5.x, acc.x); acc.y = fmaf(w5, v5.y, acc.y);
        acc.x = fmaf(w6, v6.x, acc.x); acc.y = fmaf(w6, v6.y, acc.y);
        acc.x = fmaf(w7, v7.x, acc.x); acc.y = fmaf(w7, v7.y, acc.y);
    }
    for (; j < end; j++) {
        unsigned p = __ldg(&g_edge[j]);
        float w = unpack_w(p);
        float2 v = __half22float2(__ldg(&g_y1h[(p >> 15) * 32 + lane]));
        acc.x = fmaf(w, v.x, acc.x); acc.y = fmaf(w, v.y, acc.y);
    }
    float2 h;
    h.x = fmaxf(fmaf(di, acc.x, __ldg(&b1[lane * 2])), 0.0f);
    h.y = fmaxf(fmaf(di, acc.y, __ldg(&b1[lane * 2 + 1])), 0.0f);
    *((float2*)&g_h[d * 64 + lane * 2]) = h;
}

// ---- layer-2 GEMM: y2 = h @ W2 (raw, fp16 out) ----
__global__ void __launch_bounds__(128) k_gemm2(const float* __restrict__ W2) {
    constexpr int TX = 8, TY = 16, NPB = 32;
    __shared__ float Ws[64 * 32];
    __shared__ float Xs[NPB][68];
    int tid = threadIdx.y * TX + threadIdx.x;
    {
        const float4* Wg = (const float4*)W2;
        float4* Ws4 = (float4*)Ws;
        #pragma unroll
        for (int i = tid; i < 64 * 32 / 4; i += 128) Ws4[i] = Wg[i];
    }
    int nb = blockIdx.x * NPB;
    #pragma unroll
    for (int i = tid; i < NPB * 16; i += 128) {
        int node = i >> 4, k4 = i & 15;
        *((float4*)&Xs[node][k4 * 4]) = ((const float4*)&g_h[(nb + node) * 64])[k4];
    }
    __syncthreads();

    int tx = threadIdx.x, ty = threadIdx.y;
    float4 a0 = {0,0,0,0}, a1 = {0,0,0,0};
    #pragma unroll
    for (int k = 0; k < 64; k++) {
        float4 w4 = *((const float4*)&Ws[k * 32 + tx * 4]);
        float x0 = Xs[ty][k], x1 = Xs[ty + TY][k];
        a0.x = fmaf(x0, w4.x, a0.x); a0.y = fmaf(x0, w4.y, a0.y);
        a0.z = fmaf(x0, w4.z, a0.z); a0.w = fmaf(x0, w4.w, a0.w);
        a1.x = fmaf(x1, w4.x, a1.x); a1.y = fmaf(x1, w4.y, a1.y);
        a1.z = fmaf(x1, w4.z, a1.z); a1.w = fmaf(x1, w4.w, a1.w);
    }
    int n0 = nb + ty, n1 = nb + ty + TY;
    *((__half2*)&g_y2h[n0 * 16 + tx * 2])     = __floats2half2_rn(a0.x, a0.y);
    *((__half2*)&g_y2h[n0 * 16 + tx * 2 + 1]) = __floats2half2_rn(a0.z, a0.w);
    *((__half2*)&g_y2h[n1 * 16 + tx * 2])     = __floats2half2_rn(a1.x, a1.y);
    *((__half2*)&g_y2h[n1 * 16 + tx * 2 + 1]) = __floats2half2_rn(a1.z, a1.w);
}

// ---- layer-2 aggregate + epilogue, fp16 gathers, packed edges, 8-wide ----
__global__ void __launch_bounds__(256) k_agg2(const float* __restrict__ b2,
                                              float* __restrict__ out) {
    const __half* y2 = (const __half*)g_y2h;
    int warp = (blockIdx.x * 256 + threadIdx.x) >> 5;
    if (warp >= N) return;
    int lane = threadIdx.x & 31;
    int d = warp;
    int beg = g_rs[d], end = beg + g_cnt[d];
    float di = g_dinv[d];
    float acc = di * __half2float(y2[d * 32 + lane]);   // self loop
    int j = beg;
    for (; j + 7 < end; j += 8) {
        unsigned p0 = __ldg(&g_edge[j]),     p1 = __ldg(&g_edge[j + 1]);
        unsigned p2 = __ldg(&g_edge[j + 2]), p3 = __ldg(&g_edge[j + 3]);
        unsigned p4 = __ldg(&g_edge[j + 4]), p5 = __ldg(&g_edge[j + 5]);
        unsigned p6 = __ldg(&g_edge[j + 6]), p7 = __ldg(&g_edge[j + 7]);
        float v0 = __half2float(__ldg(&y2[(p0 >> 15) * 32 + lane]));
        float v1 = __half2float(__ldg(&y2[(p1 >> 15) * 32 + lane]));
        float v2 = __half2float(__ldg(&y2[(p2 >> 15) * 32 + lane]));
        float v3 = __half2float(__ldg(&y2[(p3 >> 15) * 32 + lane]));
        float v4 = __half2float(__ldg(&y2[(p4 >> 15) * 32 + lane]));
        float v5 = __half2float(__ldg(&y2[(p5 >> 15) * 32 + lane]));
        float v6 = __half2float(__ldg(&y2[(p6 >> 15) * 32 + lane]));
        float v7 = __half2float(__ldg(&y2[(p7 >> 15) * 32 + lane]));
        acc = fmaf(unpack_w(p0), v0, acc);
        acc = fmaf(unpack_w(p1), v1, acc);
        acc = fmaf(unpack_w(p2), v2, acc);
        acc = fmaf(unpack_w(p3), v3, acc);
        acc = fmaf(unpack_w(p4), v4, acc);
        acc = fmaf(unpack_w(p5), v5, acc);
        acc = fmaf(unpack_w(p6), v6, acc);
        acc = fmaf(unpack_w(p7), v7, acc);
    }
    for (; j < end; j++) {
        unsigned p = __ldg(&g_edge[j]);
        acc = fmaf(unpack_w(p), __half2float(__ldg(&y2[(p >> 15) * 32 + lane])), acc);
    }
    out[d * 32 + lane] = fmaf(di, acc, b2[lane]);
}

extern "C" void kernel_launch(void* const* d_in, const int* in_sizes, int n_in,
                              void* d_out, int out_size) {
    const float* x  = (const float*)d_in[0];
    const int*   ei = (const int*)d_in[1];     // edge_index as int32
    const float* ew = (const float*)d_in[2];
    const float* W1 = (const float*)d_in[3];
    const float* b1 = (const float*)d_in[4];
    const float* W2 = (const float*)d_in[5];
    const float* b2 = (const float*)d_in[6];
    float* out = (float*)d_out;

    // side stream for gemm1 (independent of the prep chain)
    cudaStream_t s2;
    cudaStreamCreateWithFlags(&s2, cudaStreamNonBlocking);
    cudaEvent_t ev_fork, ev_join;
    cudaEventCreateWithFlags(&ev_fork, cudaEventDisableTiming);
    cudaEventCreateWithFlags(&ev_join, cudaEventDisableTiming);

    cudaEventRecord(ev_fork, 0);
    cudaStreamWaitEvent(s2, ev_fork, 0);
    k_gemm1<<<N / 32, dim3(16, 8), 0, s2>>>(x, W1);
    cudaEventRecord(ev_join, s2);

    // main chain
    void* p_zero = nullptr;
    cudaGetSymbolAddress(&p_zero, g_zero);
    cudaMemsetAsync(p_zero, 0, (N + NB_SCAN + 1) * sizeof(unsigned long long));
    k_prep   <<<(E / 4 + 255) / 256, 256>>>(ei, ew);
    k_scan   <<<NB_SCAN, SCAN_B>>>();
    k_reorder<<<(E / 4 + 255) / 256, 256>>>(ei, ew);

    cudaStreamWaitEvent(0, ev_join, 0);
    k_agg1   <<<(N * 32 + 255) / 256, 256>>>(b1);
    k_gemm2  <<<N / 32, dim3(8, 16)>>>(W2);
    k_agg2   <<<(N * 32 + 255) / 256, 256>>>(b2, out);
}

// round 14
// speedup vs baseline: 1.0865x; 1.0137x over previous
#include <cuda_runtime.h>
#include <cuda_fp16.h>

static constexpr int N = 100000;
static constexpr int E = 1600000;
static constexpr int SCAN_B = 512;
static constexpr int NB_SCAN = (N + SCAN_B - 1) / SCAN_B;   // 196

// node-range split for the agg1/gemm2 pipeline (multiples of 32)
static constexpr int NA = 50016;            // chunk A nodes
static constexpr int NB = N - NA;           // 49984, chunk B

// ---- zeroed-per-launch region (single memset): g_cw[N] | g_state[NB] | ticket ----
__device__ unsigned long long g_zero[N + NB_SCAN + 1];
#define g_cw     (g_zero)                  // packed: count<<40 | wdeg*2^24
#define g_state  (g_zero + N)              // lookback: flag<<62 | inclusive/aggregate
#define g_ticket (g_zero + N + NB_SCAN)

__device__ float    g_dinv[N];
__device__ int      g_cnt[N];
__device__ int      g_rs[N];
__device__ int      g_cur[N];
__device__ int2     g_edge[E];             // {src, fp32bits(w*dinv[src])}
__device__ __half2  g_y1h[N * 32];         // x @ W1, raw, fp16 (128 B/row)
__device__ float    g_h [N * 64];          // relu'd hidden, fp32
__device__ __half2  g_y2h[N * 16];         // h @ W2, raw, fp16 (64 B/row)

// ---- count + weighted degree: fire-and-forget packed u64 atomic (REDG path) ----
__global__ void k_prep(const int* __restrict__ ei, const float* __restrict__ ew) {
    int t = blockIdx.x * blockDim.x + threadIdx.x;
    int e = t * 4;
    if (e >= E) return;
    int4   d4 = *((const int4*)(ei + E + e));
    float4 w4 = *((const float4*)(ew + e));
    #pragma unroll
    for (int k = 0; k < 4; k++) {
        int d = (&d4.x)[k];
        float w = (&w4.x)[k];
        if ((unsigned)d >= (unsigned)N) d = 0;
        unsigned long long v = (1ULL << 40) |
            (unsigned long long)(unsigned int)__float2uint_rn(w * 16777216.0f);
        atomicAdd(&g_cw[d], v);            // result unused -> REDG
    }
}

// ---- single-kernel scan: decode + decoupled-lookback prefix + rs/cur/dinv ----
__global__ void __launch_bounds__(SCAN_B) k_scan() {
    __shared__ int wsum[16];
    __shared__ int sh_bid;
    __shared__ unsigned sh_excl;
    __shared__ int sh_total;
    int t = threadIdx.x, lane = t & 31, wid = t >> 5;

    if (t == 0) sh_bid = (int)atomicAdd(g_ticket, 1ULL);   // ordered tile id
    __syncthreads();
    int bid = sh_bid;
    int g = bid * SCAN_B + t;

    int v = 0;
    if (g < N) {
        unsigned long long p = g_cw[g];
        v = (int)(p >> 40);
        float wdeg = (float)(p & ((1ULL << 40) - 1)) * (1.0f / 16777216.0f);
        g_cnt[g] = v;
        g_dinv[g] = rsqrtf(1.0f + wdeg);
    }
    int s = v;
    #pragma unroll
    for (int o = 1; o < 32; o <<= 1) {
        int n = __shfl_up_sync(0xffffffffu, s, o);
        if (lane >= o) s += n;
    }
    if (lane == 31) wsum[wid] = s;
    __syncthreads();
    if (wid == 0) {
        int ws = (lane < 16) ? wsum[lane] : 0;
        #pragma unroll
        for (int o = 1; o < 16; o <<= 1) {
            int n = __shfl_up_sync(0xffffffffu, ws, o);
            if (lane >= o) ws += n;
        }
        if (lane < 16) wsum[lane] = ws;
    }
    __syncthreads();
    s += wid ? wsum[wid - 1] : 0;
    if (t == SCAN_B - 1) sh_total = s;
    __syncthreads();
    int total = sh_total;

    if (wid == 0) {
        if (lane == 0) {
            unsigned long long pub = (bid == 0)
                ? ((2ULL << 62) | (unsigned)total)
                : ((1ULL << 62) | (unsigned)total);
            atomicExch(&g_state[bid], pub);
        }
        __syncwarp();
        unsigned running = 0;
        if (bid > 0) {
            int idx = bid - 1;
            while (true) {
                int look = idx - lane;
                unsigned long long st = 0;
                if (look >= 0) {
                    do { st = atomicAdd(&g_state[look], 0ULL); }
                    while ((st >> 62) == 0);
                }
                unsigned flag = (unsigned)(st >> 62);
                unsigned val = (unsigned)(st & 0xffffffffu);
                unsigned mask_inc = __ballot_sync(0xffffffffu, look >= 0 && flag == 2u);
                if (mask_inc) {
                    int firstInc = __ffs(mask_inc) - 1;
                    unsigned c = (look >= 0 && lane <= firstInc) ? val : 0;
                    #pragma unroll
                    for (int o = 16; o > 0; o >>= 1) c += __shfl_down_sync(0xffffffffu, c, o);
                    running += __shfl_sync(0xffffffffu, c, 0);
                    break;
                } else {
                    unsigned c = (look >= 0) ? val : 0;
                    #pragma unroll
                    for (int o = 16; o > 0; o >>= 1) c += __shfl_down_sync(0xffffffffu, c, o);
                    running += __shfl_sync(0xffffffffu, c, 0);
                    idx -= 32;
                    if (idx < 0) break;
                }
            }
            if (lane == 0)
                atomicExch(&g_state[bid], (2ULL << 62) | (unsigned)(running + total));
        }
        if (lane == 0) sh_excl = running;
    }
    __syncthreads();
    int excl = (int)sh_excl;

    if (g < N) {
        int start = excl + s - v;
        g_rs[g]  = start;
        g_cur[g] = start;
    }
}

// ---- bucket edges by destination (cursor atomic), dinv[src] folded into weight ----
__global__ void k_reorder(const int* __restrict__ ei, const float* __restrict__ ew) {
    int e = blockIdx.x * blockDim.x + threadIdx.x;
    if (e >= E) return;
    int s = ei[e];
    int d = ei[E + e];
    if ((unsigned)s >= (unsigned)N) s = 0;
    if ((unsigned)d >= (unsigned)N) d = 0;
    float wp = ew[e] * __ldg(&g_dinv[s]);
    int pos = atomicAdd(&g_cur[d], 1);
    g_edge[pos] = make_int2(s, __float_as_int(wp));
}

// ---- layer-1 GEMM: y1 = x @ W1 (raw, fp16 out). Independent of prep chain. ----
__global__ void __launch_bounds__(128) k_gemm1(const float* __restrict__ X,
                                               const float* __restrict__ W) {
    constexpr int TX = 16, NPB = 32;
    __shared__ float Ws[64 * 64];
    __shared__ float Xs[NPB][68];
    int tid = threadIdx.y * TX + threadIdx.x;
    {
        const float4* Wg = (const float4*)W;
        float4* Ws4 = (float4*)Ws;
        #pragma unroll
        for (int i = tid; i < 64 * 64 / 4; i += 128) Ws4[i] = Wg[i];
    }
    int nb = blockIdx.x * NPB;                 // N % 32 == 0
    #pragma unroll
    for (int i = tid; i < NPB * 16; i += 128) {
        int node = i >> 4, k4 = i & 15;
        *((float4*)&Xs[node][k4 * 4]) = ((const float4*)(X + (nb + node) * 64))[k4];
    }
    __syncthreads();

    int tx = threadIdx.x, ty = threadIdx.y;    // ty in 0..7
    float4 a0 = {0,0,0,0}, a1 = {0,0,0,0}, a2 = {0,0,0,0}, a3 = {0,0,0,0};
    #pragma unroll
    for (int k4 = 0; k4 < 16; k4++) {
        float4 xv0 = *((const float4*)&Xs[ty][k4 * 4]);
        float4 xv1 = *((const float4*)&Xs[ty + 8][k4 * 4]);
        float4 xv2 = *((const float4*)&Xs[ty + 16][k4 * 4]);
        float4 xv3 = *((const float4*)&Xs[ty + 24][k4 * 4]);
        #pragma unroll
        for (int kk = 0; kk < 4; kk++) {
            float4 w4 = *((const float4*)&Ws[(k4 * 4 + kk) * 64 + tx * 4]);
            float x0 = (&xv0.x)[kk], x1 = (&xv1.x)[kk];
            float x2 = (&xv2.x)[kk], x3 = (&xv3.x)[kk];
            a0.x = fmaf(x0, w4.x, a0.x); a0.y = fmaf(x0, w4.y, a0.y);
            a0.z = fmaf(x0, w4.z, a0.z); a0.w = fmaf(x0, w4.w, a0.w);
            a1.x = fmaf(x1, w4.x, a1.x); a1.y = fmaf(x1, w4.y, a1.y);
            a1.z = fmaf(x1, w4.z, a1.z); a1.w = fmaf(x1, w4.w, a1.w);
            a2.x = fmaf(x2, w4.x, a2.x); a2.y = fmaf(x2, w4.y, a2.y);
            a2.z = fmaf(x2, w4.z, a2.z); a2.w = fmaf(x2, w4.w, a2.w);
            a3.x = fmaf(x3, w4.x, a3.x); a3.y = fmaf(x3, w4.y, a3.y);
            a3.z = fmaf(x3, w4.z, a3.z); a3.w = fmaf(x3, w4.w, a3.w);
        }
    }
    #pragma unroll
    for (int m = 0; m < 4; m++) {
        int n = nb + ty + 8 * m;
        float4 a = (m == 0) ? a0 : (m == 1) ? a1 : (m == 2) ? a2 : a3;
        *((__half2*)&g_y1h[n * 32 + tx * 2])     = __floats2half2_rn(a.x, a.y);
        *((__half2*)&g_y1h[n * 32 + tx * 2 + 1]) = __floats2half2_rn(a.z, a.w);
    }
}

// ---- layer-1 aggregate (warp per node), fp16 gathers, 8-wide; node-ranged ----
__global__ void __launch_bounds__(256) k_agg1(const float* __restrict__ b1,
                                              int base, int count) {
    int warp = (blockIdx.x * 256 + threadIdx.x) >> 5;
    if (warp >= count) return;
    int lane = threadIdx.x & 31;
    int d = base + warp;
    int beg = g_rs[d], end = beg + g_cnt[d];
    float di = g_dinv[d];
    float2 self = __half22float2(g_y1h[d * 32 + lane]);
    float2 acc;
    acc.x = di * self.x; acc.y = di * self.y;
    int j = beg;
    for (; j + 7 < end; j += 8) {
        int2 e0 = __ldg(&g_edge[j]),     e1 = __ldg(&g_edge[j + 1]);
        int2 e2 = __ldg(&g_edge[j + 2]), e3 = __ldg(&g_edge[j + 3]);
        int2 e4 = __ldg(&g_edge[j + 4]), e5 = __ldg(&g_edge[j + 5]);
        int2 e6 = __ldg(&g_edge[j + 6]), e7 = __ldg(&g_edge[j + 7]);
        float2 v0 = __half22float2(__ldg(&g_y1h[e0.x * 32 + lane]));
        float2 v1 = __half22float2(__ldg(&g_y1h[e1.x * 32 + lane]));
        float2 v2 = __half22float2(__ldg(&g_y1h[e2.x * 32 + lane]));
        float2 v3 = __half22float2(__ldg(&g_y1h[e3.x * 32 + lane]));
        float2 v4 = __half22float2(__ldg(&g_y1h[e4.x * 32 + lane]));
        float2 v5 = __half22float2(__ldg(&g_y1h[e5.x * 32 + lane]));
        float2 v6 = __half22float2(__ldg(&g_y1h[e6.x * 32 + lane]));
        float2 v7 = __half22float2(__ldg(&g_y1h[e7.x * 32 + lane]));
        float w0 = __int_as_float(e0.y), w1 = __int_as_float(e1.y);
        float w2 = __int_as_float(e2.y), w3 = __int_as_float(e3.y);
        float w4 = __int_as_float(e4.y), w5 = __int_as_float(e5.y);
        float w6 = __int_as_float(e6.y), w7 = __int_as_float(e7.y);
        acc.x = fmaf(w0, v0.x, acc.x); acc.y = fmaf(w0, v0.y, acc.y);
        acc.x = fmaf(w1, v1.x, acc.x); acc.y = fmaf(w1, v1.y, acc.y);
        acc.x = fmaf(w2, v2.x, acc.x); acc.y = fmaf(w2, v2.y, acc.y);
        acc.x = fmaf(w3, v3.x, acc.x); acc.y = fmaf(w3, v3.y, acc.y);
        acc.x = fmaf(w4, v4.x, acc.x); acc.y = fmaf(w4, v4.y, acc.y);
        acc.x = fmaf(w5, v5.x, acc.x); acc.y = fmaf(w5, v5.y, acc.y);
        acc.x = fmaf(w6, v6.x, acc.x); acc.y = fmaf(w6, v6.y, acc.y);
        acc.x = fmaf(w7, v7.x, acc.x); acc.y = fmaf(w7, v7.y, acc.y);
    }
    for (; j < end; j++) {
        int2 e = __ldg(&g_edge[j]);
        float w = __int_as_float(e.y);
        float2 v = __half22float2(__ldg(&g_y1h[e.x * 32 + lane]));
        acc.x = fmaf(w, v.x, acc.x); acc.y = fmaf(w, v.y, acc.y);
    }
    float2 h;
    h.x = fmaxf(fmaf(di, acc.x, __ldg(&b1[lane * 2])), 0.0f);
    h.y = fmaxf(fmaf(di, acc.y, __ldg(&b1[lane * 2 + 1])), 0.0f);
    *((float2*)&g_h[d * 64 + lane * 2]) = h;
}

// ---- layer-2 GEMM: y2 = h @ W2 (raw, fp16 out); node-ranged ----
__global__ void __launch_bounds__(128) k_gemm2(const float* __restrict__ W2, int base) {
    constexpr int TX = 8, TY = 16, NPB = 32;
    __shared__ float Ws[64 * 32];
    __shared__ float Xs[NPB][68];
    int tid = threadIdx.y * TX + threadIdx.x;
    {
        const float4* Wg = (const float4*)W2;
        float4* Ws4 = (float4*)Ws;
        #pragma unroll
        for (int i = tid; i < 64 * 32 / 4; i += 128) Ws4[i] = Wg[i];
    }
    int nb = base + blockIdx.x * NPB;
    #pragma unroll
    for (int i = tid; i < NPB * 16; i += 128) {
        int node = i >> 4, k4 = i & 15;
        *((float4*)&Xs[node][k4 * 4]) = ((const float4*)&g_h[(nb + node) * 64])[k4];
    }
    __syncthreads();

    int tx = threadIdx.x, ty = threadIdx.y;
    float4 a0 = {0,0,0,0}, a1 = {0,0,0,0};
    #pragma unroll
    for (int k = 0; k < 64; k++) {
        float4 w4 = *((const float4*)&Ws[k * 32 + tx * 4]);
        float x0 = Xs[ty][k], x1 = Xs[ty + TY][k];
        a0.x = fmaf(x0, w4.x, a0.x); a0.y = fmaf(x0, w4.y, a0.y);
        a0.z = fmaf(x0, w4.z, a0.z); a0.w = fmaf(x0, w4.w, a0.w);
        a1.x = fmaf(x1, w4.x, a1.x); a1.y = fmaf(x1, w4.y, a1.y);
        a1.z = fmaf(x1, w4.z, a1.z); a1.w = fmaf(x1, w4.w, a1.w);
    }
    int n0 = nb + ty, n1 = nb + ty + TY;
    *((__half2*)&g_y2h[n0 * 16 + tx * 2])     = __floats2half2_rn(a0.x, a0.y);
    *((__half2*)&g_y2h[n0 * 16 + tx * 2 + 1]) = __floats2half2_rn(a0.z, a0.w);
    *((__half2*)&g_y2h[n1 * 16 + tx * 2])     = __floats2half2_rn(a1.x, a1.y);
    *((__half2*)&g_y2h[n1 * 16 + tx * 2 + 1]) = __floats2half2_rn(a1.z, a1.w);
}

// ---- layer-2 aggregate + epilogue, fp16 gathers, 8-wide ----
__global__ void __launch_bounds__(256) k_agg2(const float* __restrict__ b2,
                                              float* __restrict__ out) {
    const __half* y2 = (const __half*)g_y2h;
    int warp = (blockIdx.x * 256 + threadIdx.x) >> 5;
    if (warp >= N) return;
    int lane = threadIdx.x & 31;
    int d = warp;
    int beg = g_rs[d], end = beg + g_cnt[d];
    float di = g_dinv[d];
    float acc = di * __half2float(y2[d * 32 + lane]);   // self loop
    int j = beg;
    for (; j + 7 < end; j += 8) {
        int2 e0 = __ldg(&g_edge[j]),     e1 = __ldg(&g_edge[j + 1]);
        int2 e2 = __ldg(&g_edge[j + 2]), e3 = __ldg(&g_edge[j + 3]);
        int2 e4 = __ldg(&g_edge[j + 4]), e5 = __ldg(&g_edge[j + 5]);
        int2 e6 = __ldg(&g_edge[j + 6]), e7 = __ldg(&g_edge[j + 7]);
        float v0 = __half2float(__ldg(&y2[e0.x * 32 + lane]));
        float v1 = __half2float(__ldg(&y2[e1.x * 32 + lane]));
        float v2 = __half2float(__ldg(&y2[e2.x * 32 + lane]));
        float v3 = __half2float(__ldg(&y2[e3.x * 32 + lane]));
        float v4 = __half2float(__ldg(&y2[e4.x * 32 + lane]));
        float v5 = __half2float(__ldg(&y2[e5.x * 32 + lane]));
        float v6 = __half2float(__ldg(&y2[e6.x * 32 + lane]));
        float v7 = __half2float(__ldg(&y2[e7.x * 32 + lane]));
        acc = fmaf(__int_as_float(e0.y), v0, acc);
        acc = fmaf(__int_as_float(e1.y), v1, acc);
        acc = fmaf(__int_as_float(e2.y), v2, acc);
        acc = fmaf(__int_as_float(e3.y), v3, acc);
        acc = fmaf(__int_as_float(e4.y), v4, acc);
        acc = fmaf(__int_as_float(e5.y), v5, acc);
        acc = fmaf(__int_as_float(e6.y), v6, acc);
        acc = fmaf(__int_as_float(e7.y), v7, acc);
    }
    for (; j < end; j++) {
        int2 e = __ldg(&g_edge[j]);
        acc = fmaf(__int_as_float(e.y), __half2float(__ldg(&y2[e.x * 32 + lane])), acc);
    }
    out[d * 32 + lane] = fmaf(di, acc, b2[lane]);
}

extern "C" void kernel_launch(void* const* d_in, const int* in_sizes, int n_in,
                              void* d_out, int out_size) {
    const float* x  = (const float*)d_in[0];
    const int*   ei = (const int*)d_in[1];     // edge_index as int32
    const float* ew = (const float*)d_in[2];
    const float* W1 = (const float*)d_in[3];
    const float* b1 = (const float*)d_in[4];
    const float* W2 = (const float*)d_in[5];
    const float* b2 = (const float*)d_in[6];
    float* out = (float*)d_out;

    // side stream: gemm1 (independent), later gemm2_A (pipelined with agg1_B)
    cudaStream_t s2;
    cudaStreamCreateWithFlags(&s2, cudaStreamNonBlocking);
    cudaEvent_t ev_fork, ev_g1, ev_a1a, ev_g2a;
    cudaEventCreateWithFlags(&ev_fork, cudaEventDisableTiming);
    cudaEventCreateWithFlags(&ev_g1,   cudaEventDisableTiming);
    cudaEventCreateWithFlags(&ev_a1a,  cudaEventDisableTiming);
    cudaEventCreateWithFlags(&ev_g2a,  cudaEventDisableTiming);

    cudaEventRecord(ev_fork, 0);
    cudaStreamWaitEvent(s2, ev_fork, 0);
    k_gemm1<<<N / 32, dim3(16, 8), 0, s2>>>(x, W1);
    cudaEventRecord(ev_g1, s2);

    // main chain: CSR build
    void* p_zero = nullptr;
    cudaGetSymbolAddress(&p_zero, g_zero);
    cudaMemsetAsync(p_zero, 0, (N + NB_SCAN + 1) * sizeof(unsigned long long));
    k_prep   <<<(E / 4 + 255) / 256, 256>>>(ei, ew);
    k_scan   <<<NB_SCAN, SCAN_B>>>();
    k_reorder<<<(E + 255) / 256, 256>>>(ei, ew);

    // agg1 chunk A (needs gemm1 + reorder), then overlap gemm2_A with agg1_B
    cudaStreamWaitEvent(0, ev_g1, 0);
    k_agg1<<<NA / 8, 256>>>(b1, 0, NA);
    cudaEventRecord(ev_a1a, 0);
    k_agg1<<<NB / 8, 256>>>(b1, NA, NB);

    cudaStreamWaitEvent(s2, ev_a1a, 0);
    k_gemm2<<<NA / 32, dim3(8, 16), 0, s2>>>(W2, 0);
    cudaEventRecord(ev_g2a, s2);

    k_gemm2<<<NB / 32, dim3(8, 16)>>>(W2, NA);

    cudaStreamWaitEvent(0, ev_g2a, 0);
    k_agg2<<<(N * 32 + 255) / 256, 256>>>(b2, out);
}

// round 15
// speedup vs baseline: 1.0951x; 1.0079x over previous
#include <cuda_runtime.h>
#include <cuda_fp16.h>

static constexpr int N = 100000;
static constexpr int E = 1600000;
static constexpr int SCAN_B = 512;
static constexpr int NB_SCAN = (N + SCAN_B - 1) / SCAN_B;   // 196

// ---- zeroed-per-launch region (single memset): g_cw[N] | g_state[NB] | ticket ----
__device__ unsigned long long g_zero[N + NB_SCAN + 1];
#define g_cw     (g_zero)                  // packed: count<<40 | wdeg*2^24
#define g_state  (g_zero + N)              // lookback: flag<<62 | inclusive/aggregate
#define g_ticket (g_zero + N + NB_SCAN)

__device__ float    g_dinv[N];
__device__ __half   g_dinvh[N];            // fp16 dinv: 200KB, L1-resident in reorder
__device__ int      g_cnt[N];
__device__ int      g_rs[N];
__device__ int      g_cur[N];
__device__ int2     g_edge[E];             // {src, fp32bits(w*dinv[src])}
__device__ __half2  g_y1h[N * 32];         // x @ W1, raw, fp16 (128 B/row)
__device__ float    g_h [N * 64];          // relu'd hidden, fp32
__device__ __half2  g_y2h[N * 16];         // h @ W2, raw, fp16 (64 B/row)

// ---- count + weighted degree: fire-and-forget packed u64 atomic (REDG path) ----
__global__ void k_prep(const int* __restrict__ ei, const float* __restrict__ ew) {
    int t = blockIdx.x * blockDim.x + threadIdx.x;
    int e = t * 4;
    if (e >= E) return;
    int4   d4 = *((const int4*)(ei + E + e));
    float4 w4 = *((const float4*)(ew + e));
    #pragma unroll
    for (int k = 0; k < 4; k++) {
        int d = (&d4.x)[k];
        float w = (&w4.x)[k];
        if ((unsigned)d >= (unsigned)N) d = 0;
        unsigned long long v = (1ULL << 40) |
            (unsigned long long)(unsigned int)__float2uint_rn(w * 16777216.0f);
        atomicAdd(&g_cw[d], v);            // result unused -> REDG
    }
}

// ---- single-kernel scan: decode + decoupled-lookback prefix + rs/cur/dinv ----
__global__ void __launch_bounds__(SCAN_B) k_scan() {
    __shared__ int wsum[16];
    __shared__ int sh_bid;
    __shared__ unsigned sh_excl;
    __shared__ int sh_total;
    int t = threadIdx.x, lane = t & 31, wid = t >> 5;

    if (t == 0) sh_bid = (int)atomicAdd(g_ticket, 1ULL);   // ordered tile id
    __syncthreads();
    int bid = sh_bid;
    int g = bid * SCAN_B + t;

    int v = 0;
    if (g < N) {
        unsigned long long p = g_cw[g];
        v = (int)(p >> 40);
        float wdeg = (float)(p & ((1ULL << 40) - 1)) * (1.0f / 16777216.0f);
        float di = rsqrtf(1.0f + wdeg);
        g_cnt[g] = v;
        g_dinv[g] = di;
        g_dinvh[g] = __float2half_rn(di);
    }
    int s = v;
    #pragma unroll
    for (int o = 1; o < 32; o <<= 1) {
        int n = __shfl_up_sync(0xffffffffu, s, o);
        if (lane >= o) s += n;
    }
    if (lane == 31) wsum[wid] = s;
    __syncthreads();
    if (wid == 0) {
        int ws = (lane < 16) ? wsum[lane] : 0;
        #pragma unroll
        for (int o = 1; o < 16; o <<= 1) {
            int n = __shfl_up_sync(0xffffffffu, ws, o);
            if (lane >= o) ws += n;
        }
        if (lane < 16) wsum[lane] = ws;
    }
    __syncthreads();
    s += wid ? wsum[wid - 1] : 0;
    if (t == SCAN_B - 1) sh_total = s;
    __syncthreads();
    int total = sh_total;

    if (wid == 0) {
        if (lane == 0) {
            unsigned long long pub = (bid == 0)
                ? ((2ULL << 62) | (unsigned)total)
                : ((1ULL << 62) | (unsigned)total);
            atomicExch(&g_state[bid], pub);
        }
        __syncwarp();
        unsigned running = 0;
        if (bid > 0) {
            int idx = bid - 1;
            while (true) {
                int look = idx - lane;
                unsigned long long st = 0;
                if (look >= 0) {
                    do { st = atomicAdd(&g_state[look], 0ULL); }
                    while ((st >> 62) == 0);
                }
                unsigned flag = (unsigned)(st >> 62);
                unsigned val = (unsigned)(st & 0xffffffffu);
                unsigned mask_inc = __ballot_sync(0xffffffffu, look >= 0 && flag == 2u);
                if (mask_inc) {
                    int firstInc = __ffs(mask_inc) - 1;
                    unsigned c = (look >= 0 && lane <= firstInc) ? val : 0;
                    #pragma unroll
                    for (int o = 16; o > 0; o >>= 1) c += __shfl_down_sync(0xffffffffu, c, o);
                    running += __shfl_sync(0xffffffffu, c, 0);
                    break;
                } else {
                    unsigned c = (look >= 0) ? val : 0;
                    #pragma unroll
                    for (int o = 16; o > 0; o >>= 1) c += __shfl_down_sync(0xffffffffu, c, o);
                    running += __shfl_sync(0xffffffffu, c, 0);
                    idx -= 32;
                    if (idx < 0) break;
                }
            }
            if (lane == 0)
                atomicExch(&g_state[bid], (2ULL << 62) | (unsigned)(running + total));
        }
        if (lane == 0) sh_excl = running;
    }
    __syncthreads();
    int excl = (int)sh_excl;

    if (g < N) {
        int start = excl + s - v;
        g_rs[g]  = start;
        g_cur[g] = start;
    }
}

// ---- bucket edges by destination; dinv[src] from L1-resident fp16 table ----
__global__ void k_reorder(const int* __restrict__ ei, const float* __restrict__ ew) {
    int e = blockIdx.x * blockDim.x + threadIdx.x;
    if (e >= E) return;
    int s = ei[e];
    int d = ei[E + e];
    if ((unsigned)s >= (unsigned)N) s = 0;
    if ((unsigned)d >= (unsigned)N) d = 0;
    float wp = ew[e] * __half2float(__ldg(&g_dinvh[s]));
    int pos = atomicAdd(&g_cur[d], 1);
    g_edge[pos] = make_int2(s, __float_as_int(wp));
}

// ---- layer-1 GEMM: y1 = x @ W1 (raw, fp16 out). Independent of prep chain. ----
__global__ void __launch_bounds__(128) k_gemm1(const float* __restrict__ X,
                                               const float* __restrict__ W) {
    constexpr int TX = 16, NPB = 32;
    __shared__ float Ws[64 * 64];
    __shared__ float Xs[NPB][68];
    int tid = threadIdx.y * TX + threadIdx.x;
    {
        const float4* Wg = (const float4*)W;
        float4* Ws4 = (float4*)Ws;
        #pragma unroll
        for (int i = tid; i < 64 * 64 / 4; i += 128) Ws4[i] = Wg[i];
    }
    int nb = blockIdx.x * NPB;                 // N % 32 == 0
    #pragma unroll
    for (int i = tid; i < NPB * 16; i += 128) {
        int node = i >> 4, k4 = i & 15;
        *((float4*)&Xs[node][k4 * 4]) = ((const float4*)(X + (nb + node) * 64))[k4];
    }
    __syncthreads();

    int tx = threadIdx.x, ty = threadIdx.y;    // ty in 0..7
    float4 a0 = {0,0,0,0}, a1 = {0,0,0,0}, a2 = {0,0,0,0}, a3 = {0,0,0,0};
    #pragma unroll
    for (int k4 = 0; k4 < 16; k4++) {
        float4 xv0 = *((const float4*)&Xs[ty][k4 * 4]);
        float4 xv1 = *((const float4*)&Xs[ty + 8][k4 * 4]);
        float4 xv2 = *((const float4*)&Xs[ty + 16][k4 * 4]);
        float4 xv3 = *((const float4*)&Xs[ty + 24][k4 * 4]);
        #pragma unroll
        for (int kk = 0; kk < 4; kk++) {
            float4 w4 = *((const float4*)&Ws[(k4 * 4 + kk) * 64 + tx * 4]);
            float x0 = (&xv0.x)[kk], x1 = (&xv1.x)[kk];
            float x2 = (&xv2.x)[kk], x3 = (&xv3.x)[kk];
            a0.x = fmaf(x0, w4.x, a0.x); a0.y = fmaf(x0, w4.y, a0.y);
            a0.z = fmaf(x0, w4.z, a0.z); a0.w = fmaf(x0, w4.w, a0.w);
            a1.x = fmaf(x1, w4.x, a1.x); a1.y = fmaf(x1, w4.y, a1.y);
            a1.z = fmaf(x1, w4.z, a1.z); a1.w = fmaf(x1, w4.w, a1.w);
            a2.x = fmaf(x2, w4.x, a2.x); a2.y = fmaf(x2, w4.y, a2.y);
            a2.z = fmaf(x2, w4.z, a2.z); a2.w = fmaf(x2, w4.w, a2.w);
            a3.x = fmaf(x3, w4.x, a3.x); a3.y = fmaf(x3, w4.y, a3.y);
            a3.z = fmaf(x3, w4.z, a3.z); a3.w = fmaf(x3, w4.w, a3.w);
        }
    }
    #pragma unroll
    for (int m = 0; m < 4; m++) {
        int n = nb + ty + 8 * m;
        float4 a = (m == 0) ? a0 : (m == 1) ? a1 : (m == 2) ? a2 : a3;
        *((__half2*)&g_y1h[n * 32 + tx * 2])     = __floats2half2_rn(a.x, a.y);
        *((__half2*)&g_y1h[n * 32 + tx * 2 + 1]) = __floats2half2_rn(a.z, a.w);
    }
}

// ---- layer-1 aggregate (warp per node), fp16 gathers, 8-wide ----
__global__ void __launch_bounds__(256) k_agg1(const float* __restrict__ b1) {
    int warp = (blockIdx.x * 256 + threadIdx.x) >> 5;
    if (warp >= N) return;
    int lane = threadIdx.x & 31;
    int d = warp;
    int beg = g_rs[d], end = beg + g_cnt[d];
    float di = g_dinv[d];
    float2 self = __half22float2(g_y1h[d * 32 + lane]);
    float2 acc;
    acc.x = di * self.x; acc.y = di * self.y;
    int j = beg;
    for (; j + 7 < end; j += 8) {
        int2 e0 = __ldg(&g_edge[j]),     e1 = __ldg(&g_edge[j + 1]);
        int2 e2 = __ldg(&g_edge[j + 2]), e3 = __ldg(&g_edge[j + 3]);
        int2 e4 = __ldg(&g_edge[j + 4]), e5 = __ldg(&g_edge[j + 5]);
        int2 e6 = __ldg(&g_edge[j + 6]), e7 = __ldg(&g_edge[j + 7]);
        float2 v0 = __half22float2(__ldg(&g_y1h[e0.x * 32 + lane]));
        float2 v1 = __half22float2(__ldg(&g_y1h[e1.x * 32 + lane]));
        float2 v2 = __half22float2(__ldg(&g_y1h[e2.x * 32 + lane]));
        float2 v3 = __half22float2(__ldg(&g_y1h[e3.x * 32 + lane]));
        float2 v4 = __half22float2(__ldg(&g_y1h[e4.x * 32 + lane]));
        float2 v5 = __half22float2(__ldg(&g_y1h[e5.x * 32 + lane]));
        float2 v6 = __half22float2(__ldg(&g_y1h[e6.x * 32 + lane]));
        float2 v7 = __half22float2(__ldg(&g_y1h[e7.x * 32 + lane]));
        float w0 = __int_as_float(e0.y), w1 = __int_as_float(e1.y);
        float w2 = __int_as_float(e2.y), w3 = __int_as_float(e3.y);
        float w4 = __int_as_float(e4.y), w5 = __int_as_float(e5.y);
        float w6 = __int_as_float(e6.y), w7 = __int_as_float(e7.y);
        acc.x = fmaf(w0, v0.x, acc.x); acc.y = fmaf(w0, v0.y, acc.y);
        acc.x = fmaf(w1, v1.x, acc.x); acc.y = fmaf(w1, v1.y, acc.y);
        acc.x = fmaf(w2, v2.x, acc.x); acc.y = fmaf(w2, v2.y, acc.y);
        acc.x = fmaf(w3, v3.x, acc.x); acc.y = fmaf(w3, v3.y, acc.y);
        acc.x = fmaf(w4, v4.x, acc.x); acc.y = fmaf(w4, v4.y, acc.y);
        acc.x = fmaf(w5, v5.x, acc.x); acc.y = fmaf(w5, v5.y, acc.y);
        acc.x = fmaf(w6, v6.x, acc.x); acc.y = fmaf(w6, v6.y, acc.y);
        acc.x = fmaf(w7, v7.x, acc.x); acc.y = fmaf(w7, v7.y, acc.y);
    }
    for (; j < end; j++) {
        int2 e = __ldg(&g_edge[j]);
        float w = __int_as_float(e.y);
        float2 v = __half22float2(__ldg(&g_y1h[e.x * 32 + lane]));
        acc.x = fmaf(w, v.x, acc.x); acc.y = fmaf(w, v.y, acc.y);
    }
    float2 h;
    h.x = fmaxf(fmaf(di, acc.x, __ldg(&b1[lane * 2])), 0.0f);
    h.y = fmaxf(fmaf(di, acc.y, __ldg(&b1[lane * 2 + 1])), 0.0f);
    *((float2*)&g_h[d * 64 + lane * 2]) = h;
}

// ---- layer-2 GEMM: y2 = h @ W2 (raw, fp16 out) ----
__global__ void __launch_bounds__(128) k_gemm2(const float* __restrict__ W2) {
    constexpr int TX = 8, TY = 16, NPB = 32;
    __shared__ float Ws[64 * 32];
    __shared__ float Xs[NPB][68];
    int tid = threadIdx.y * TX + threadIdx.x;
    {
        const float4* Wg = (const float4*)W2;
        float4* Ws4 = (float4*)Ws;
        #pragma unroll
        for (int i = tid; i < 64 * 32 / 4; i += 128) Ws4[i] = Wg[i];
    }
    int nb = blockIdx.x * NPB;
    #pragma unroll
    for (int i = tid; i < NPB * 16; i += 128) {
        int node = i >> 4, k4 = i & 15;
        *((float4*)&Xs[node][k4 * 4]) = ((const float4*)&g_h[(nb + node) * 64])[k4];
    }
    __syncthreads();

    int tx = threadIdx.x, ty = threadIdx.y;
    float4 a0 = {0,0,0,0}, a1 = {0,0,0,0};
    #pragma unroll
    for (int k = 0; k < 64; k++) {
        float4 w4 = *((const float4*)&Ws[k * 32 + tx * 4]);
        float x0 = Xs[ty][k], x1 = Xs[ty + TY][k];
        a0.x = fmaf(x0, w4.x, a0.x); a0.y = fmaf(x0, w4.y, a0.y);
        a0.z = fmaf(x0, w4.z, a0.z); a0.w = fmaf(x0, w4.w, a0.w);
        a1.x = fmaf(x1, w4.x, a1.x); a1.y = fmaf(x1, w4.y, a1.y);
        a1.z = fmaf(x1, w4.z, a1.z); a1.w = fmaf(x1, w4.w, a1.w);
    }
    int n0 = nb + ty, n1 = nb + ty + TY;
    *((__half2*)&g_y2h[n0 * 16 + tx * 2])     = __floats2half2_rn(a0.x, a0.y);
    *((__half2*)&g_y2h[n0 * 16 + tx * 2 + 1]) = __floats2half2_rn(a0.z, a0.w);
    *((__half2*)&g_y2h[n1 * 16 + tx * 2])     = __floats2half2_rn(a1.x, a1.y);
    *((__half2*)&g_y2h[n1 * 16 + tx * 2 + 1]) = __floats2half2_rn(a1.z, a1.w);
}

// ---- layer-2 aggregate + epilogue, fp16 gathers, 8-wide ----
__global__ void __launch_bounds__(256) k_agg2(const float* __restrict__ b2,
                                              float* __restrict__ out) {
    const __half* y2 = (const __half*)g_y2h;
    int warp = (blockIdx.x * 256 + threadIdx.x) >> 5;
    if (warp >= N) return;
    int lane = threadIdx.x & 31;
    int d = warp;
    int beg = g_rs[d], end = beg + g_cnt[d];
    float di = g_dinv[d];
    float acc = di * __half2float(y2[d * 32 + lane]);   // self loop
    int j = beg;
    for (; j + 7 < end; j += 8) {
        int2 e0 = __ldg(&g_edge[j]),     e1 = __ldg(&g_edge[j + 1]);
        int2 e2 = __ldg(&g_edge[j + 2]), e3 = __ldg(&g_edge[j + 3]);
        int2 e4 = __ldg(&g_edge[j + 4]), e5 = __ldg(&g_edge[j + 5]);
        int2 e6 = __ldg(&g_edge[j + 6]), e7 = __ldg(&g_edge[j + 7]);
        float v0 = __half2float(__ldg(&y2[e0.x * 32 + lane]));
        float v1 = __half2float(__ldg(&y2[e1.x * 32 + lane]));
        float v2 = __half2float(__ldg(&y2[e2.x * 32 + lane]));
        float v3 = __half2float(__ldg(&y2[e3.x * 32 + lane]));
        float v4 = __half2float(__ldg(&y2[e4.x * 32 + lane]));
        float v5 = __half2float(__ldg(&y2[e5.x * 32 + lane]));
        float v6 = __half2float(__ldg(&y2[e6.x * 32 + lane]));
        float v7 = __half2float(__ldg(&y2[e7.x * 32 + lane]));
        acc = fmaf(__int_as_float(e0.y), v0, acc);
        acc = fmaf(__int_as_float(e1.y), v1, acc);
        acc = fmaf(__int_as_float(e2.y), v2, acc);
        acc = fmaf(__int_as_float(e3.y), v3, acc);
        acc = fmaf(__int_as_float(e4.y), v4, acc);
        acc = fmaf(__int_as_float(e5.y), v5, acc);
        acc = fmaf(__int_as_float(e6.y), v6, acc);
        acc = fmaf(__int_as_float(e7.y), v7, acc);
    }
    for (; j < end; j++) {
        int2 e = __ldg(&g_edge[j]);
        acc = fmaf(__int_as_float(e.y), __half2float(__ldg(&y2[e.x * 32 + lane])), acc);
    }
    out[d * 32 + lane] = fmaf(di, acc, b2[lane]);
}

extern "C" void kernel_launch(void* const* d_in, const int* in_sizes, int n_in,
                              void* d_out, int out_size) {
    const float* x  = (const float*)d_in[0];
    const int*   ei = (const int*)d_in[1];     // edge_index as int32
    const float* ew = (const float*)d_in[2];
    const float* W1 = (const float*)d_in[3];
    const float* b1 = (const float*)d_in[4];
    const float* W2 = (const float*)d_in[5];
    const float* b2 = (const float*)d_in[6];
    float* out = (float*)d_out;

    // side stream for gemm1 (independent of the prep chain)
    cudaStream_t s2;
    cudaStreamCreateWithFlags(&s2, cudaStreamNonBlocking);
    cudaEvent_t ev_fork, ev_join;
    cudaEventCreateWithFlags(&ev_fork, cudaEventDisableTiming);
    cudaEventCreateWithFlags(&ev_join, cudaEventDisableTiming);

    cudaEventRecord(ev_fork, 0);
    cudaStreamWaitEvent(s2, ev_fork, 0);
    k_gemm1<<<N / 32, dim3(16, 8), 0, s2>>>(x, W1);
    cudaEventRecord(ev_join, s2);

    // main chain
    void* p_zero = nullptr;
    cudaGetSymbolAddress(&p_zero, g_zero);
    cudaMemsetAsync(p_zero, 0, (N + NB_SCAN + 1) * sizeof(unsigned long long));
    k_prep   <<<(E / 4 + 255) / 256, 256>>>(ei, ew);
    k_scan   <<<NB_SCAN, SCAN_B>>>();
    k_reorder<<<(E + 255) / 256, 256>>>(ei, ew);

    cudaStreamWaitEvent(0, ev_join, 0);
    k_agg1   <<<(N * 32 + 255) / 256, 256>>>(b1);
    k_gemm2  <<<N / 32, dim3(8, 16)>>>(W2);
    k_agg2   <<<(N * 32 + 255) / 256, 256>>>(b2, out);
}

// round 17
// speedup vs baseline: 1.1382x; 1.0393x over previous
#include <cuda_runtime.h>
#include <cuda_fp16.h>

static constexpr int N = 100000;
static constexpr int E = 1600000;
static constexpr int SCAN_B = 512;
static constexpr int NB_SCAN = (N + SCAN_B - 1) / SCAN_B;   // 196

// ---- zeroed-per-launch region (single memset): g_cw[N] | g_state[NB] | ticket ----
__device__ unsigned long long g_zero[N + NB_SCAN + 1];
#define g_cw     (g_zero)                  // packed: count<<40 | wdeg*2^24
#define g_state  (g_zero + N)              // lookback: flag<<62 | inclusive/aggregate
#define g_ticket (g_zero + N + NB_SCAN)

__device__ float    g_dinv[N];
__device__ __half   g_dinvh[N];            // fp16 dinv for reorder's gather
__device__ int      g_cnt[N];
__device__ int      g_rs[N];
__device__ int      g_cur[N];
__device__ int2     g_edge[E];             // {src, fp32bits(w*dinv[src])}
__device__ __half2  g_y1h[N * 32];         // x @ W1, raw, fp16 (128 B/row)
__device__ __half2  g_hh [N * 32];         // relu'd hidden, fp16 (128 B/row)
__device__ __half2  g_y2h[N * 16];         // h @ W2, raw, fp16 (64 B/row)

// ---- count + weighted degree: fire-and-forget packed u64 atomic (REDG path) ----
__global__ void k_prep(const int* __restrict__ ei, const float* __restrict__ ew) {
    int t = blockIdx.x * blockDim.x + threadIdx.x;
    int e = t * 4;
    if (e >= E) return;
    int4   d4 = *((const int4*)(ei + E + e));
    float4 w4 = *((const float4*)(ew + e));
    #pragma unroll
    for (int k = 0; k < 4; k++) {
        int d = (&d4.x)[k];
        float w = (&w4.x)[k];
        if ((unsigned)d >= (unsigned)N) d = 0;
        unsigned long long v = (1ULL << 40) |
            (unsigned long long)(unsigned int)__float2uint_rn(w * 16777216.0f);
        atomicAdd(&g_cw[d], v);            // result unused -> REDG
    }
}

// ---- single-kernel scan: decode + decoupled-lookback prefix + rs/cur/dinv ----
__global__ void __launch_bounds__(SCAN_B) k_scan() {
    __shared__ int wsum[16];
    __shared__ int sh_bid;
    __shared__ unsigned sh_excl;
    __shared__ int sh_total;
    int t = threadIdx.x, lane = t & 31, wid = t >> 5;

    if (t == 0) sh_bid = (int)atomicAdd(g_ticket, 1ULL);   // ordered tile id
    __syncthreads();
    int bid = sh_bid;
    int g = bid * SCAN_B + t;

    int v = 0;
    if (g < N) {
        unsigned long long p = g_cw[g];
        v = (int)(p >> 40);
        float wdeg = (float)(p & ((1ULL << 40) - 1)) * (1.0f / 16777216.0f);
        float di = rsqrtf(1.0f + wdeg);
        g_cnt[g] = v;
        g_dinv[g] = di;
        g_dinvh[g] = __float2half_rn(di);
    }
    int s = v;
    #pragma unroll
    for (int o = 1; o < 32; o <<= 1) {
        int n = __shfl_up_sync(0xffffffffu, s, o);
        if (lane >= o) s += n;
    }
    if (lane == 31) wsum[wid] = s;
    __syncthreads();
    if (wid == 0) {
        int ws = (lane < 16) ? wsum[lane] : 0;
        #pragma unroll
        for (int o = 1; o < 16; o <<= 1) {
            int n = __shfl_up_sync(0xffffffffu, ws, o);
            if (lane >= o) ws += n;
        }
        if (lane < 16) wsum[lane] = ws;
    }
    __syncthreads();
    s += wid ? wsum[wid - 1] : 0;
    if (t == SCAN_B - 1) sh_total = s;
    __syncthreads();
    int total = sh_total;

    if (wid == 0) {
        if (lane == 0) {
            unsigned long long pub = (bid == 0)
                ? ((2ULL << 62) | (unsigned)total)
                : ((1ULL << 62) | (unsigned)total);
            atomicExch(&g_state[bid], pub);
        }
        __syncwarp();
        unsigned running = 0;
        if (bid > 0) {
            int idx = bid - 1;
            while (true) {
                int look = idx - lane;
                unsigned long long st = 0;
                if (look >= 0) {
                    do { st = atomicAdd(&g_state[look], 0ULL); }
                    while ((st >> 62) == 0);
                }
                unsigned flag = (unsigned)(st >> 62);
                unsigned val = (unsigned)(st & 0xffffffffu);
                unsigned mask_inc = __ballot_sync(0xffffffffu, look >= 0 && flag == 2u);
                if (mask_inc) {
                    int firstInc = __ffs(mask_inc) - 1;
                    unsigned c = (look >= 0 && lane <= firstInc) ? val : 0;
                    #pragma unroll
                    for (int o = 16; o > 0; o >>= 1) c += __shfl_down_sync(0xffffffffu, c, o);
                    running += __shfl_sync(0xffffffffu, c, 0);
                    break;
                } else {
                    unsigned c = (look >= 0) ? val : 0;
                    #pragma unroll
                    for (int o = 16; o > 0; o >>= 1) c += __shfl_down_sync(0xffffffffu, c, o);
                    running += __shfl_sync(0xffffffffu, c, 0);
                    idx -= 32;
                    if (idx < 0) break;
                }
            }
            if (lane == 0)
                atomicExch(&g_state[bid], (2ULL << 62) | (unsigned)(running + total));
        }
        if (lane == 0) sh_excl = running;
    }
    __syncthreads();
    int excl = (int)sh_excl;

    if (g < N) {
        int start = excl + s - v;
        g_rs[g]  = start;
        g_cur[g] = start;
    }
}

// ---- bucket edges by destination; dinv[src] from fp16 table ----
__global__ void k_reorder(const int* __restrict__ ei, const float* __restrict__ ew) {
    int e = blockIdx.x * blockDim.x + threadIdx.x;
    if (e >= E) return;
    int s = ei[e];
    int d = ei[E + e];
    if ((unsigned)s >= (unsigned)N) s = 0;
    if ((unsigned)d >= (unsigned)N) d = 0;
    float wp = ew[e] * __half2float(__ldg(&g_dinvh[s]));
    int pos = atomicAdd(&g_cur[d], 1);
    g_edge[pos] = make_int2(s, __float_as_int(wp));
}

// ---- layer-1 GEMM: y1 = x @ W1 (raw, fp16 out). Independent of prep chain. ----
__global__ void __launch_bounds__(128) k_gemm1(const float* __restrict__ X,
                                               const float* __restrict__ W) {
    constexpr int TX = 16, NPB = 32;
    __shared__ float Ws[64 * 64];
    __shared__ float Xs[NPB][68];
    int tid = threadIdx.y * TX + threadIdx.x;
    {
        const float4* Wg = (const float4*)W;
        float4* Ws4 = (float4*)Ws;
        #pragma unroll
        for (int i = tid; i < 64 * 64 / 4; i += 128) Ws4[i] = Wg[i];
    }
    int nb = blockIdx.x * NPB;                 // N % 32 == 0
    #pragma unroll
    for (int i = tid; i < NPB * 16; i += 128) {
        int node = i >> 4, k4 = i & 15;
        *((float4*)&Xs[node][k4 * 4]) = ((const float4*)(X + (nb + node) * 64))[k4];
    }
    __syncthreads();

    int tx = threadIdx.x, ty = threadIdx.y;    // ty in 0..7
    float4 a0 = {0,0,0,0}, a1 = {0,0,0,0}, a2 = {0,0,0,0}, a3 = {0,0,0,0};
    #pragma unroll
    for (int k4 = 0; k4 < 16; k4++) {
        float4 xv0 = *((const float4*)&Xs[ty][k4 * 4]);
        float4 xv1 = *((const float4*)&Xs[ty + 8][k4 * 4]);
        float4 xv2 = *((const float4*)&Xs[ty + 16][k4 * 4]);
        float4 xv3 = *((const float4*)&Xs[ty + 24][k4 * 4]);
        #pragma unroll
        for (int kk = 0; kk < 4; kk++) {
            float4 w4 = *((const float4*)&Ws[(k4 * 4 + kk) * 64 + tx * 4]);
            float x0 = (&xv0.x)[kk], x1 = (&xv1.x)[kk];
            float x2 = (&xv2.x)[kk], x3 = (&xv3.x)[kk];
            a0.x = fmaf(x0, w4.x, a0.x); a0.y = fmaf(x0, w4.y, a0.y);
            a0.z = fmaf(x0, w4.z, a0.z); a0.w = fmaf(x0, w4.w, a0.w);
            a1.x = fmaf(x1, w4.x, a1.x); a1.y = fmaf(x1, w4.y, a1.y);
            a1.z = fmaf(x1, w4.z, a1.z); a1.w = fmaf(x1, w4.w, a1.w);
            a2.x = fmaf(x2, w4.x, a2.x); a2.y = fmaf(x2, w4.y, a2.y);
            a2.z = fmaf(x2, w4.z, a2.z); a2.w = fmaf(x2, w4.w, a2.w);
            a3.x = fmaf(x3, w4.x, a3.x); a3.y = fmaf(x3, w4.y, a3.y);
            a3.z = fmaf(x3, w4.z, a3.z); a3.w = fmaf(x3, w4.w, a3.w);
        }
    }
    #pragma unroll
    for (int m = 0; m < 4; m++) {
        int n = nb + ty + 8 * m;
        float4 a = (m == 0) ? a0 : (m == 1) ? a1 : (m == 2) ? a2 : a3;
        *((__half2*)&g_y1h[n * 32 + tx * 2])     = __floats2half2_rn(a.x, a.y);
        *((__half2*)&g_y1h[n * 32 + tx * 2 + 1]) = __floats2half2_rn(a.z, a.w);
    }
}

// ---- layer-1 aggregate (warp per node), fp16 gathers, tiered 8/4/2/1 unroll ----
__global__ void __launch_bounds__(256) k_agg1(const float* __restrict__ b1) {
    int warp = (blockIdx.x * 256 + threadIdx.x) >> 5;
    if (warp >= N) return;
    int lane = threadIdx.x & 31;
    int d = warp;
    int beg = g_rs[d], end = beg + g_cnt[d];
    float di = g_dinv[d];
    float2 self = __half22float2(g_y1h[d * 32 + lane]);
    float2 acc;
    acc.x = di * self.x; acc.y = di * self.y;
    int j = beg;
    for (; j + 7 < end; j += 8) {
        int2 e0 = __ldg(&g_edge[j]),     e1 = __ldg(&g_edge[j + 1]);
        int2 e2 = __ldg(&g_edge[j + 2]), e3 = __ldg(&g_edge[j + 3]);
        int2 e4 = __ldg(&g_edge[j + 4]), e5 = __ldg(&g_edge[j + 5]);
        int2 e6 = __ldg(&g_edge[j + 6]), e7 = __ldg(&g_edge[j + 7]);
        float2 v0 = __half22float2(__ldg(&g_y1h[e0.x * 32 + lane]));
        float2 v1 = __half22float2(__ldg(&g_y1h[e1.x * 32 + lane]));
        float2 v2 = __half22float2(__ldg(&g_y1h[e2.x * 32 + lane]));
        float2 v3 = __half22float2(__ldg(&g_y1h[e3.x * 32 + lane]));
        float2 v4 = __half22float2(__ldg(&g_y1h[e4.x * 32 + lane]));
        float2 v5 = __half22float2(__ldg(&g_y1h[e5.x * 32 + lane]));
        float2 v6 = __half22float2(__ldg(&g_y1h[e6.x * 32 + lane]));
        float2 v7 = __half22float2(__ldg(&g_y1h[e7.x * 32 + lane]));
        float w0 = __int_as_float(e0.y), w1 = __int_as_float(e1.y);
        float w2 = __int_as_float(e2.y), w3 = __int_as_float(e3.y);
        float w4 = __int_as_float(e4.y), w5 = __int_as_float(e5.y);
        float w6 = __int_as_float(e6.y), w7 = __int_as_float(e7.y);
        acc.x = fmaf(w0, v0.x, acc.x); acc.y = fmaf(w0, v0.y, acc.y);
        acc.x = fmaf(w1, v1.x, acc.x); acc.y = fmaf(w1, v1.y, acc.y);
        acc.x = fmaf(w2, v2.x, acc.x); acc.y = fmaf(w2, v2.y, acc.y);
        acc.x = fmaf(w3, v3.x, acc.x); acc.y = fmaf(w3, v3.y, acc.y);
        acc.x = fmaf(w4, v4.x, acc.x); acc.y = fmaf(w4, v4.y, acc.y);
        acc.x = fmaf(w5, v5.x, acc.x); acc.y = fmaf(w5, v5.y, acc.y);
        acc.x = fmaf(w6, v6.x, acc.x); acc.y = fmaf(w6, v6.y, acc.y);
        acc.x = fmaf(w7, v7.x, acc.x); acc.y = fmaf(w7, v7.y, acc.y);
    }
    if (j + 3 < end) {
        int2 e0 = __ldg(&g_edge[j]),     e1 = __ldg(&g_edge[j + 1]);
        int2 e2 = __ldg(&g_edge[j + 2]), e3 = __ldg(&g_edge[j + 3]);
        float2 v0 = __half22float2(__ldg(&g_y1h[e0.x * 32 + lane]));
        float2 v1 = __half22float2(__ldg(&g_y1h[e1.x * 32 + lane]));
        float2 v2 = __half22float2(__ldg(&g_y1h[e2.x * 32 + lane]));
        float2 v3 = __half22float2(__ldg(&g_y1h[e3.x * 32 + lane]));
        float w0 = __int_as_float(e0.y), w1 = __int_as_float(e1.y);
        float w2 = __int_as_float(e2.y), w3 = __int_as_float(e3.y);
        acc.x = fmaf(w0, v0.x, acc.x); acc.y = fmaf(w0, v0.y, acc.y);
        acc.x = fmaf(w1, v1.x, acc.x); acc.y = fmaf(w1, v1.y, acc.y);
        acc.x = fmaf(w2, v2.x, acc.x); acc.y = fmaf(w2, v2.y, acc.y);
        acc.x = fmaf(w3, v3.x, acc.x); acc.y = fmaf(w3, v3.y, acc.y);
        j += 4;
    }
    if (j + 1 < end) {
        int2 e0 = __ldg(&g_edge[j]), e1 = __ldg(&g_edge[j + 1]);
        float2 v0 = __half22float2(__ldg(&g_y1h[e0.x * 32 + lane]));
        float2 v1 = __half22float2(__ldg(&g_y1h[e1.x * 32 + lane]));
        float w0 = __int_as_float(e0.y), w1 = __int_as_float(e1.y);
        acc.x = fmaf(w0, v0.x, acc.x); acc.y = fmaf(w0, v0.y, acc.y);
        acc.x = fmaf(w1, v1.x, acc.x); acc.y = fmaf(w1, v1.y, acc.y);
        j += 2;
    }
    if (j < end) {
        int2 e = __ldg(&g_edge[j]);
        float w = __int_as_float(e.y);
        float2 v = __half22float2(__ldg(&g_y1h[e.x * 32 + lane]));
        acc.x = fmaf(w, v.x, acc.x); acc.y = fmaf(w, v.y, acc.y);
    }
    float2 h;
    h.x = fmaxf(fmaf(di, acc.x, __ldg(&b1[lane * 2])), 0.0f);
    h.y = fmaxf(fmaf(di, acc.y, __ldg(&b1[lane * 2 + 1])), 0.0f);
    g_hh[d * 32 + lane] = __floats2half2_rn(h.x, h.y);
}

// ---- layer-2 GEMM: y2 = h @ W2 (h in fp16, fp32 accumulate, fp16 out) ----
__global__ void __launch_bounds__(128) k_gemm2(const float* __restrict__ W2) {
    constexpr int TX = 8, TY = 16, NPB = 32;
    __shared__ float Ws[64 * 32];
    __shared__ float Xs[NPB][68];
    int tid = threadIdx.y * TX + threadIdx.x;
    {
        const float4* Wg = (const float4*)W2;
        float4* Ws4 = (float4*)W2 ? (float4*)Ws : (float4*)Ws;
        #pragma unroll
        for (int i = tid; i < 64 * 32 / 4; i += 128) Ws4[i] = Wg[i];
    }
    int nb = blockIdx.x * NPB;
    #pragma unroll
    for (int i = tid; i < NPB * 16; i += 128) {
        int node = i >> 4, k4 = i & 15;
        // 4 halves = 8 bytes per (node, k4) group
        int2 raw = ((const int2*)&g_hh[(nb + node) * 32])[k4];
        float2 f0 = __half22float2(*(__half2*)&raw.x);
        float2 f1 = __half22float2(*(__half2*)&raw.y);
        Xs[node][k4 * 4 + 0] = f0.x;
        Xs[node][k4 * 4 + 1] = f0.y;
        Xs[node][k4 * 4 + 2] = f1.x;
        Xs[node][k4 * 4 + 3] = f1.y;
    }
    __syncthreads();

    int tx = threadIdx.x, ty = threadIdx.y;
    float4 a0 = {0,0,0,0}, a1 = {0,0,0,0};
    #pragma unroll
    for (int k = 0; k < 64; k++) {
        float4 w4 = *((const float4*)&Ws[k * 32 + tx * 4]);
        float x0 = Xs[ty][k], x1 = Xs[ty + TY][k];
        a0.x = fmaf(x0, w4.x, a0.x); a0.y = fmaf(x0, w4.y, a0.y);
        a0.z = fmaf(x0, w4.z, a0.z); a0.w = fmaf(x0, w4.w, a0.w);
        a1.x = fmaf(x1, w4.x, a1.x); a1.y = fmaf(x1, w4.y, a1.y);
        a1.z = fmaf(x1, w4.z, a1.z); a1.w = fmaf(x1, w4.w, a1.w);
    }
    int n0 = nb + ty, n1 = nb + ty + TY;
    *((__half2*)&g_y2h[n0 * 16 + tx * 2])     = __floats2half2_rn(a0.x, a0.y);
    *((__half2*)&g_y2h[n0 * 16 + tx * 2 + 1]) = __floats2half2_rn(a0.z, a0.w);
    *((__half2*)&g_y2h[n1 * 16 + tx * 2])     = __floats2half2_rn(a1.x, a1.y);
    *((__half2*)&g_y2h[n1 * 16 + tx * 2 + 1]) = __floats2half2_rn(a1.z, a1.w);
}

// ---- layer-2 aggregate + epilogue, fp16 gathers, tiered 8/4/2/1 unroll ----
__global__ void __launch_bounds__(256) k_agg2(const float* __restrict__ b2,
                                              float* __restrict__ out) {
    const __half* y2 = (const __half*)g_y2h;
    int warp = (blockIdx.x * 256 + threadIdx.x) >> 5;
    if (warp >= N) return;
    int lane = threadIdx.x & 31;
    int d = warp;
    int beg = g_rs[d], end = beg + g_cnt[d];
    float di = g_dinv[d];
    float acc = di * __half2float(y2[d * 32 + lane]);   // self loop
    int j = beg;
    for (; j + 7 < end; j += 8) {
        int2 e0 = __ldg(&g_edge[j]),     e1 = __ldg(&g_edge[j + 1]);
        int2 e2 = __ldg(&g_edge[j + 2]), e3 = __ldg(&g_edge[j + 3]);
        int2 e4 = __ldg(&g_edge[j + 4]), e5 = __ldg(&g_edge[j + 5]);
        int2 e6 = __ldg(&g_edge[j + 6]), e7 = __ldg(&g_edge[j + 7]);
        float v0 = __half2float(__ldg(&y2[e0.x * 32 + lane]));
        float v1 = __half2float(__ldg(&y2[e1.x * 32 + lane]));
        float v2 = __half2float(__ldg(&y2[e2.x * 32 + lane]));
        float v3 = __half2float(__ldg(&y2[e3.x * 32 + lane]));
        float v4 = __half2float(__ldg(&y2[e4.x * 32 + lane]));
        float v5 = __half2float(__ldg(&y2[e5.x * 32 + lane]));
        float v6 = __half2float(__ldg(&y2[e6.x * 32 + lane]));
        float v7 = __half2float(__ldg(&y2[e7.x * 32 + lane]));
        acc = fmaf(__int_as_float(e0.y), v0, acc);
        acc = fmaf(__int_as_float(e1.y), v1, acc);
        acc = fmaf(__int_as_float(e2.y), v2, acc);
        acc = fmaf(__int_as_float(e3.y), v3, acc);
        acc = fmaf(__int_as_float(e4.y), v4, acc);
        acc = fmaf(__int_as_float(e5.y), v5, acc);
        acc = fmaf(__int_as_float(e6.y), v6, acc);
        acc = fmaf(__int_as_float(e7.y), v7, acc);
    }
    if (j + 3 < end) {
        int2 e0 = __ldg(&g_edge[j]),     e1 = __ldg(&g_edge[j + 1]);
        int2 e2 = __ldg(&g_edge[j + 2]), e3 = __ldg(&g_edge[j + 3]);
        float v0 = __half2float(__ldg(&y2[e0.x * 32 + lane]));
        float v1 = __half2float(__ldg(&y2[e1.x * 32 + lane]));
        float v2 = __half2float(__ldg(&y2[e2.x * 32 + lane]));
        float v3 = __half2float(__ldg(&y2[e3.x * 32 + lane]));
        acc = fmaf(__int_as_float(e0.y), v0, acc);
        acc = fmaf(__int_as_float(e1.y), v1, acc);
        acc = fmaf(__int_as_float(e2.y), v2, acc);
        acc = fmaf(__int_as_float(e3.y), v3, acc);
        j += 4;
    }
    if (j + 1 < end) {
        int2 e0 = __ldg(&g_edge[j]), e1 = __ldg(&g_edge[j + 1]);
        float v0 = __half2float(__ldg(&y2[e0.x * 32 + lane]));
        float v1 = __half2float(__ldg(&y2[e1.x * 32 + lane]));
        acc = fmaf(__int_as_float(e0.y), v0, acc);
        acc = fmaf(__int_as_float(e1.y), v1, acc);
        j += 2;
    }
    if (j < end) {
        int2 e = __ldg(&g_edge[j]);
        acc = fmaf(__int_as_float(e.y), __half2float(__ldg(&y2[e.x * 32 + lane])), acc);
    }
    out[d * 32 + lane] = fmaf(di, acc, b2[lane]);
}

extern "C" void kernel_launch(void* const* d_in, const int* in_sizes, int n_in,
                              void* d_out, int out_size) {
    const float* x  = (const float*)d_in[0];
    const int*   ei = (const int*)d_in[1];     // edge_index as int32
    const float* ew = (const float*)d_in[2];
    const float* W1 = (const float*)d_in[3];
    const float* b1 = (const float*)d_in[4];
    const float* W2 = (const float*)d_in[5];
    const float* b2 = (const float*)d_in[6];
    float* out = (float*)d_out;

    // side stream for gemm1 (independent of the prep chain)
    cudaStream_t s2;
    cudaStreamCreateWithFlags(&s2, cudaStreamNonBlocking);
    cudaEvent_t ev_fork, ev_join;
    cudaEventCreateWithFlags(&ev_fork, cudaEventDisableTiming);
    cudaEventCreateWithFlags(&ev_join, cudaEventDisableTiming);

    cudaEventRecord(ev_fork, 0);
    cudaStreamWaitEvent(s2, ev_fork, 0);
    k_gemm1<<<N / 32, dim3(16, 8), 0, s2>>>(x, W1);
    cudaEventRecord(ev_join, s2);

    // main chain
    void* p_zero = nullptr;
    cudaGetSymbolAddress(&p_zero, g_zero);
    cudaMemsetAsync(p_zero, 0, (N + NB_SCAN + 1) * sizeof(unsigned long long));
    k_prep   <<<(E / 4 + 255) / 256, 256>>>(ei, ew);
    k_scan   <<<NB_SCAN, SCAN_B>>>();
    k_reorder<<<(E + 255) / 256, 256>>>(ei, ew);

    cudaStreamWaitEvent(0, ev_join, 0);
    k_agg1   <<<(N * 32 + 255) / 256, 256>>>(b1);
    k_gemm2  <<<N / 32, dim3(8, 16)>>>(W2);
    k_agg2   <<<(N * 32 + 255) / 256, 256>>>(b2, out);
}